// round 1
// baseline (speedup 1.0000x reference)
#include <cuda_runtime.h>
#include <math.h>

#define TOK   8192
#define EMBD  768
#define DFF2  3072
#define NHEAD 8
#define HD    96
#define SEQ   2048
#define NBATCH 4

// ---------------- scratch (device globals: no allocation allowed) ----------
__device__ float g_y [TOK * EMBD];
__device__ float g_q [TOK * EMBD];
__device__ float g_k [TOK * EMBD];
__device__ float g_v [TOK * EMBD];
__device__ float g_o [TOK * EMBD];
__device__ float g_x1[TOK * EMBD];
__device__ float g_z [TOK * EMBD];
__device__ float g_h [TOK * DFF2];

// ---------------- LayerNorm: one block per row of 768 ----------------------
__global__ __launch_bounds__(256)
void ln_kernel(const float* __restrict__ x, const float* __restrict__ g,
               const float* __restrict__ b, float* __restrict__ y) {
    const int row = blockIdx.x;
    const float* xr = x + (long)row * EMBD;
    const int t = threadIdx.x;
    float v0 = xr[t], v1 = xr[t + 256], v2 = xr[t + 512];
    float s  = v0 + v1 + v2;
    float sq = v0 * v0 + v1 * v1 + v2 * v2;
    #pragma unroll
    for (int o = 16; o; o >>= 1) {
        s  += __shfl_xor_sync(0xffffffffu, s,  o);
        sq += __shfl_xor_sync(0xffffffffu, sq, o);
    }
    __shared__ float sbuf[16];
    const int w = t >> 5, l = t & 31;
    if (l == 0) { sbuf[w] = s; sbuf[w + 8] = sq; }
    __syncthreads();
    float ts = 0.f, tsq = 0.f;
    #pragma unroll
    for (int i = 0; i < 8; i++) { ts += sbuf[i]; tsq += sbuf[8 + i]; }
    const float mu  = ts * (1.0f / EMBD);
    const float var = tsq * (1.0f / EMBD) - mu * mu;
    const float r   = rsqrtf(var + 1e-5f);
    float* yr = y + (long)row * EMBD;
    yr[t]       = (v0 - mu) * r * g[t]       + b[t];
    yr[t + 256] = (v1 - mu) * r * g[t + 256] + b[t + 256];
    yr[t + 512] = (v2 - mu) * r * g[t + 512] + b[t + 512];
}

// ---------------- fp32 SGEMM: C[M,N] = A[M,K] @ W[K,N] + bias, epilogues ----
// EPI: 0 = bias only, 1 = bias + residual add, 2 = bias + exact GELU
template <int EPI>
__global__ __launch_bounds__(256)
void gemm_kernel(const float* __restrict__ A, const float* __restrict__ W,
                 const float* __restrict__ bias, const float* __restrict__ res,
                 float* __restrict__ C, int M, int N, int K) {
    __shared__ float As[16][128];
    __shared__ float Bs[16][64];
    const int t  = threadIdx.x;
    const int tx = t & 15;   // N micro index
    const int ty = t >> 4;   // M micro index
    const int bm = blockIdx.y * 128;
    const int bn = blockIdx.x * 64;

    const int arow = t >> 2;          // 0..63
    const int acol = (t & 3) << 2;    // 0,4,8,12
    const int brow = t >> 4;          // 0..15
    const int bcol = (t & 15) << 2;   // 0..60

    const float* Ap0 = A + (long)(bm + arow) * K + acol;
    const float* Ap1 = A + (long)(bm + arow + 64) * K + acol;
    const float* Wp  = W + (long)brow * N + (bn + bcol);

    float acc[8][4];
    #pragma unroll
    for (int i = 0; i < 8; i++)
        #pragma unroll
        for (int j = 0; j < 4; j++) acc[i][j] = 0.f;

    for (int k0 = 0; k0 < K; k0 += 16) {
        float4 a0 = *(const float4*)(Ap0 + k0);
        float4 a1 = *(const float4*)(Ap1 + k0);
        float4 bv = *(const float4*)(Wp + (long)k0 * N);
        As[acol + 0][arow] = a0.x; As[acol + 1][arow] = a0.y;
        As[acol + 2][arow] = a0.z; As[acol + 3][arow] = a0.w;
        As[acol + 0][arow + 64] = a1.x; As[acol + 1][arow + 64] = a1.y;
        As[acol + 2][arow + 64] = a1.z; As[acol + 3][arow + 64] = a1.w;
        *(float4*)&Bs[brow][bcol] = bv;
        __syncthreads();
        #pragma unroll
        for (int k = 0; k < 16; k++) {
            float4 a0v = *(const float4*)&As[k][ty * 8];
            float4 a1v = *(const float4*)&As[k][ty * 8 + 4];
            float4 b4  = *(const float4*)&Bs[k][tx * 4];
            float am[8] = {a0v.x, a0v.y, a0v.z, a0v.w, a1v.x, a1v.y, a1v.z, a1v.w};
            float bm4[4] = {b4.x, b4.y, b4.z, b4.w};
            #pragma unroll
            for (int i = 0; i < 8; i++)
                #pragma unroll
                for (int j = 0; j < 4; j++)
                    acc[i][j] += am[i] * bm4[j];
        }
        __syncthreads();
    }

    #pragma unroll
    for (int i = 0; i < 8; i++) {
        const long r = bm + ty * 8 + i;
        #pragma unroll
        for (int j = 0; j < 4; j++) {
            const int c = bn + tx * 4 + j;
            float vv = acc[i][j] + bias[c];
            if (EPI == 1) vv += res[r * N + c];
            if (EPI == 2) vv = 0.5f * vv * (1.0f + erff(vv * 0.70710678118654752f));
            C[r * N + c] = vv;
        }
    }
}

// ---------------- Flash attention, fp32 ------------------------------------
// NOTE: reference applies softmax FIRST, then /sqrt(768). That's a pure
// output scale: O = (1/sqrt(768)) * softmax(Q K^T) @ V  (scale=1 in softmax).
#define ATT_BM 64
#define ATT_BN 64
#define SPAD   100     // padded row stride for Q/K/V tiles (96 -> 100)
#define SSTR   65      // padded row stride for S tile
#define ATT_SMEM ((3 * ATT_BM * SPAD + ATT_BM * SSTR) * (int)sizeof(float))

__global__ __launch_bounds__(256)
void attn_kernel(const float* __restrict__ Q, const float* __restrict__ K,
                 const float* __restrict__ V, float* __restrict__ O) {
    extern __shared__ float sm[];
    float* sQ = sm;
    float* sK = sQ + ATT_BM * SPAD;
    float* sV = sK + ATT_BM * SPAD;
    float* sS = sV + ATT_BM * SPAD;

    const int b  = blockIdx.z;
    const int h  = blockIdx.y;
    const int qt = blockIdx.x;
    const int tid = threadIdx.x;
    const int row = tid >> 2;      // 0..63, q row within tile
    const int sub = tid & 3;       // 4 threads cooperate per row
    const int ds  = sub * 24;      // this thread's d-slice [ds, ds+24)

    const long baseQ  = ((long)(b * SEQ + qt * ATT_BM)) * EMBD + h * HD;
    const long baseKV = ((long)(b * SEQ)) * EMBD + h * HD;

    // load Q tile (64 x 96), padded rows
    for (int i = tid; i < ATT_BM * 24; i += 256) {
        int r = i / 24, c4 = i % 24;
        *(float4*)&sQ[r * SPAD + c4 * 4] =
            *(const float4*)(Q + baseQ + (long)r * EMBD + c4 * 4);
    }

    float o[24];
    #pragma unroll
    for (int j = 0; j < 24; j++) o[j] = 0.f;
    float m = -1e30f, l = 0.f;

    for (int kt = 0; kt < SEQ / ATT_BN; kt++) {
        __syncthreads();   // protect sK/sV (and first-iter sQ load)
        for (int i = tid; i < ATT_BN * 24; i += 256) {
            int r = i / 24, c4 = i % 24;
            const long go = baseKV + (long)(kt * ATT_BN + r) * EMBD + c4 * 4;
            *(float4*)&sK[r * SPAD + c4 * 4] = *(const float4*)(K + go);
            *(float4*)&sV[r * SPAD + c4 * 4] = *(const float4*)(V + go);
        }
        __syncthreads();

        // S row: 16 columns per thread, c = j*4 + sub (conflict-free)
        float s[16];
        #pragma unroll
        for (int j = 0; j < 16; j++) s[j] = 0.f;
        #pragma unroll 4
        for (int d4 = 0; d4 < 24; d4++) {
            float4 qv = *(const float4*)&sQ[row * SPAD + d4 * 4];
            #pragma unroll
            for (int j = 0; j < 16; j++) {
                const int c = j * 4 + sub;
                float4 kv = *(const float4*)&sK[c * SPAD + d4 * 4];
                s[j] += qv.x * kv.x + qv.y * kv.y + qv.z * kv.z + qv.w * kv.w;
            }
        }

        // online softmax (scale = 1)
        float tmax = -1e30f;
        #pragma unroll
        for (int j = 0; j < 16; j++) tmax = fmaxf(tmax, s[j]);
        tmax = fmaxf(tmax, __shfl_xor_sync(0xffffffffu, tmax, 1));
        tmax = fmaxf(tmax, __shfl_xor_sync(0xffffffffu, tmax, 2));
        const float mnew = fmaxf(m, tmax);
        const float corr = __expf(m - mnew);
        float rsum = 0.f;
        #pragma unroll
        for (int j = 0; j < 16; j++) {
            float p = __expf(s[j] - mnew);
            rsum += p;
            sS[row * SSTR + j * 4 + sub] = p;
        }
        rsum += __shfl_xor_sync(0xffffffffu, rsum, 1);
        rsum += __shfl_xor_sync(0xffffffffu, rsum, 2);
        l = l * corr + rsum;
        m = mnew;
        #pragma unroll
        for (int j = 0; j < 24; j++) o[j] *= corr;
        __syncwarp();   // sS row written/read within one warp

        // O += P @ V   (each thread: its row, its 24 d-columns)
        #pragma unroll 4
        for (int k = 0; k < ATT_BN; k++) {
            const float p = sS[row * SSTR + k];
            #pragma unroll
            for (int j4 = 0; j4 < 6; j4++) {
                float4 vv = *(const float4*)&sV[k * SPAD + ds + j4 * 4];
                o[j4 * 4 + 0] += p * vv.x;
                o[j4 * 4 + 1] += p * vv.y;
                o[j4 * 4 + 2] += p * vv.z;
                o[j4 * 4 + 3] += p * vv.w;
            }
        }
        __syncwarp();
    }

    const float scale = 1.0f / (l * 27.712812921102035f);  // 1/(l*sqrt(768))
    #pragma unroll
    for (int j4 = 0; j4 < 6; j4++) {
        float4 out;
        out.x = o[j4 * 4 + 0] * scale;
        out.y = o[j4 * 4 + 1] * scale;
        out.z = o[j4 * 4 + 2] * scale;
        out.w = o[j4 * 4 + 3] * scale;
        *(float4*)(O + baseQ + (long)row * EMBD + ds + j4 * 4) = out;
    }
}

// ---------------- launch ----------------------------------------------------
extern "C" void kernel_launch(void* const* d_in, const int* in_sizes, int n_in,
                              void* d_out, int out_size) {
    const float* x     = (const float*)d_in[0];
    const float* ln1_g = (const float*)d_in[1];
    const float* ln1_b = (const float*)d_in[2];
    const float* wq    = (const float*)d_in[3];
    const float* bq    = (const float*)d_in[4];
    const float* wk    = (const float*)d_in[5];
    const float* bk    = (const float*)d_in[6];
    const float* wv    = (const float*)d_in[7];
    const float* bv    = (const float*)d_in[8];
    const float* wo    = (const float*)d_in[9];
    const float* bo    = (const float*)d_in[10];
    const float* ln2_g = (const float*)d_in[11];
    const float* ln2_b = (const float*)d_in[12];
    const float* w1    = (const float*)d_in[13];
    const float* b1    = (const float*)d_in[14];
    const float* w2    = (const float*)d_in[15];
    const float* b2    = (const float*)d_in[16];

    float *y, *q, *k, *v, *o, *x1, *z, *hbuf;
    cudaGetSymbolAddress((void**)&y,    g_y);
    cudaGetSymbolAddress((void**)&q,    g_q);
    cudaGetSymbolAddress((void**)&k,    g_k);
    cudaGetSymbolAddress((void**)&v,    g_v);
    cudaGetSymbolAddress((void**)&o,    g_o);
    cudaGetSymbolAddress((void**)&x1,   g_x1);
    cudaGetSymbolAddress((void**)&z,    g_z);
    cudaGetSymbolAddress((void**)&hbuf, g_h);

    cudaFuncSetAttribute(attn_kernel,
                         cudaFuncAttributeMaxDynamicSharedMemorySize, ATT_SMEM);

    // LN1
    ln_kernel<<<TOK, 256>>>(x, ln1_g, ln1_b, y);
    // QKV projections
    gemm_kernel<0><<<dim3(EMBD / 64, TOK / 128), 256>>>(y, wq, bq, nullptr, q, TOK, EMBD, EMBD);
    gemm_kernel<0><<<dim3(EMBD / 64, TOK / 128), 256>>>(y, wk, bk, nullptr, k, TOK, EMBD, EMBD);
    gemm_kernel<0><<<dim3(EMBD / 64, TOK / 128), 256>>>(y, wv, bv, nullptr, v, TOK, EMBD, EMBD);
    // attention
    attn_kernel<<<dim3(SEQ / ATT_BM, NHEAD, NBATCH), 256, ATT_SMEM>>>(q, k, v, o);
    // output projection + residual
    gemm_kernel<1><<<dim3(EMBD / 64, TOK / 128), 256>>>(o, wo, bo, x, x1, TOK, EMBD, EMBD);
    // LN2
    ln_kernel<<<TOK, 256>>>(x1, ln2_g, ln2_b, z);
    // FFN
    gemm_kernel<2><<<dim3(DFF2 / 64, TOK / 128), 256>>>(z, w1, b1, nullptr, hbuf, TOK, DFF2, EMBD);
    gemm_kernel<1><<<dim3(EMBD / 64, TOK / 128), 256>>>(hbuf, w2, b2, x1, (float*)d_out, TOK, EMBD, DFF2);
}

// round 3
// speedup vs baseline: 1.4942x; 1.4942x over previous
#include <cuda_runtime.h>
#include <math.h>
#include <stdint.h>

#define TOK   8192
#define EMBD  768
#define DFF2  3072
#define NHEAD 8
#define HD    96
#define SEQ   2048
#define NBATCH 4

// ---------------- scratch (device globals: no allocation allowed) ----------
__device__ float g_y [TOK * EMBD];
__device__ float g_q [TOK * EMBD];
__device__ float g_k [TOK * EMBD];
__device__ float g_v [TOK * EMBD];
__device__ float g_o [TOK * EMBD];
__device__ float g_x1[TOK * EMBD];
__device__ float g_z [TOK * EMBD];
__device__ float g_h [TOK * DFF2];

// ---------------- LayerNorm --------------------------------------------------
__global__ __launch_bounds__(256)
void ln_kernel(const float* __restrict__ x, const float* __restrict__ g,
               const float* __restrict__ b, float* __restrict__ y) {
    const int row = blockIdx.x;
    const float* xr = x + (long)row * EMBD;
    const int t = threadIdx.x;
    float v0 = xr[t], v1 = xr[t + 256], v2 = xr[t + 512];
    float s  = v0 + v1 + v2;
    float sq = v0 * v0 + v1 * v1 + v2 * v2;
    #pragma unroll
    for (int o = 16; o; o >>= 1) {
        s  += __shfl_xor_sync(0xffffffffu, s,  o);
        sq += __shfl_xor_sync(0xffffffffu, sq, o);
    }
    __shared__ float sbuf[16];
    const int w = t >> 5, l = t & 31;
    if (l == 0) { sbuf[w] = s; sbuf[w + 8] = sq; }
    __syncthreads();
    float ts = 0.f, tsq = 0.f;
    #pragma unroll
    for (int i = 0; i < 8; i++) { ts += sbuf[i]; tsq += sbuf[8 + i]; }
    const float mu  = ts * (1.0f / EMBD);
    const float var = tsq * (1.0f / EMBD) - mu * mu;
    const float r   = rsqrtf(var + 1e-5f);
    float* yr = y + (long)row * EMBD;
    yr[t]       = (v0 - mu) * r * g[t]       + b[t];
    yr[t + 256] = (v1 - mu) * r * g[t + 256] + b[t + 256];
    yr[t + 512] = (v2 - mu) * r * g[t + 512] + b[t + 512];
}

// =================== tf32 mma.sync GEMM: C = A[M,K] @ W[K,N] =================
// EPI: 0 = +bias, 1 = +bias+residual, 2 = +bias, exact GELU

__device__ __forceinline__ void cpasync16(uint32_t saddr, const void* gaddr) {
    asm volatile("cp.async.cg.shared.global [%0], [%1], 16;" :: "r"(saddr), "l"(gaddr));
}
#define CP_COMMIT() asm volatile("cp.async.commit_group;" ::: "memory")

__device__ __forceinline__ uint32_t smem_u32(const void* p) {
    uint32_t a;
    asm("{ .reg .u64 t; cvta.to.shared.u64 t, %1; cvt.u32.u64 %0, t; }"
        : "=r"(a) : "l"(p));
    return a;
}

__device__ __forceinline__ void mma_tf32(float* c, const uint32_t* a, const uint32_t* b) {
    asm volatile(
        "mma.sync.aligned.m16n8k8.row.col.f32.tf32.tf32.f32 "
        "{%0,%1,%2,%3}, {%4,%5,%6,%7}, {%8,%9}, {%0,%1,%2,%3};"
        : "+f"(c[0]), "+f"(c[1]), "+f"(c[2]), "+f"(c[3])
        : "r"(a[0]), "r"(a[1]), "r"(a[2]), "r"(a[3]), "r"(b[0]), "r"(b[1]));
}

#define GK        32                  // K per stage
#define A_STR     36                  // A smem row stride (floats), conflict-free
#define B_STR     136                 // B smem row stride (floats), conflict-free
#define A_BYTES   (128 * A_STR * 4)   // 18432
#define B_BYTES   (GK * B_STR * 4)    // 17408
#define STG_BYTES (A_BYTES + B_BYTES) // 35840
#define GM_SMEM   (2 * STG_BYTES)

// load one stage: A[bm..bm+127][k0..k0+31], W[k0..k0+31][bn..bn+127]
__device__ __forceinline__ void ld_stage(uint32_t sa, uint32_t sb,
                                         const float* __restrict__ A,
                                         const float* __restrict__ W,
                                         int bm, int bn, int K, int N, int k0,
                                         int tid) {
    #pragma unroll
    for (int j = 0; j < 4; j++) {
        const int ch = tid + j * 256;           // 0..1023
        const int m = ch >> 3, k4 = ch & 7;     // 128 rows x 8 chunks
        cpasync16(sa + (m * A_STR + k4 * 4) * 4,
                  A + (long)(bm + m) * K + k0 + k4 * 4);
    }
    #pragma unroll
    for (int j = 0; j < 4; j++) {
        const int ch = tid + j * 256;
        const int r = ch >> 5, c = ch & 31;     // 32 rows x 32 chunks
        cpasync16(sb + (r * B_STR + c * 4) * 4,
                  W + (long)(k0 + r) * N + bn + c * 4);
    }
}

template <int EPI>
__global__ __launch_bounds__(256, 1)
void gemm_mma(const float* __restrict__ A, const float* __restrict__ W,
              const float* __restrict__ bias, const float* __restrict__ res,
              float* __restrict__ C, int M, int N, int K) {
    extern __shared__ float smf[];
    const uint32_t sbase = smem_u32(smf);

    const int tid  = threadIdx.x;
    const int lane = tid & 31;
    const int wid  = tid >> 5;
    const int bm = blockIdx.y * 128;
    const int bn = blockIdx.x * 128;
    const int wm = (wid & 1) * 64;       // warp M origin (4 x 16)
    const int wn = (wid >> 1) * 32;      // warp N origin (4 x 8)

    const int rA = wm + (lane >> 2);     // A frag row base
    const int cA = lane & 3;             // A frag col base (k)
    const int nB = wn + (lane >> 2);     // B frag n base

    float acc[4][4][4];
    #pragma unroll
    for (int mi = 0; mi < 4; mi++)
        #pragma unroll
        for (int ni = 0; ni < 4; ni++)
            #pragma unroll
            for (int u = 0; u < 4; u++) acc[mi][ni][u] = 0.f;

    const int nkt = K / GK;
    ld_stage(sbase, sbase + A_BYTES, A, W, bm, bn, K, N, 0, tid);
    CP_COMMIT();

    for (int kt = 0; kt < nkt; kt++) {
        const uint32_t sa = sbase + (kt & 1) * STG_BYTES;
        const float* fA = (const float*)(smf) + (kt & 1) * (STG_BYTES / 4);
        const float* fB = fA + A_BYTES / 4;

        if (kt + 1 < nkt) {
            const uint32_t sn = sbase + ((kt + 1) & 1) * STG_BYTES;
            ld_stage(sn, sn + A_BYTES, A, W, bm, bn, K, N, (kt + 1) * GK, tid);
            CP_COMMIT();
            asm volatile("cp.async.wait_group 1;" ::: "memory");
        } else {
            asm volatile("cp.async.wait_group 0;" ::: "memory");
        }
        __syncthreads();

        #pragma unroll
        for (int ks = 0; ks < 4; ks++) {
            uint32_t af[4][4];
            #pragma unroll
            for (int mi = 0; mi < 4; mi++) {
                const float* p = fA + (rA + mi * 16) * A_STR + ks * 8 + cA;
                af[mi][0] = __float_as_uint(p[0]);
                af[mi][1] = __float_as_uint(p[8 * A_STR]);
                af[mi][2] = __float_as_uint(p[4]);
                af[mi][3] = __float_as_uint(p[8 * A_STR + 4]);
            }
            uint32_t bf[4][2];
            #pragma unroll
            for (int ni = 0; ni < 4; ni++) {
                const float* p = fB + (ks * 8 + cA) * B_STR + nB + ni * 8;
                bf[ni][0] = __float_as_uint(p[0]);
                bf[ni][1] = __float_as_uint(p[4 * B_STR]);
            }
            #pragma unroll
            for (int mi = 0; mi < 4; mi++)
                #pragma unroll
                for (int ni = 0; ni < 4; ni++)
                    mma_tf32(acc[mi][ni], af[mi], bf[ni]);
        }
        __syncthreads();
    }

    // epilogue: c0,c1 -> (row, col), c2,c3 -> (row+8, col); col = 2*(lane&3)
    const int erow = bm + wm + (lane >> 2);
    const int ecol = bn + wn + (lane & 3) * 2;
    #pragma unroll
    for (int mi = 0; mi < 4; mi++) {
        #pragma unroll
        for (int half = 0; half < 2; half++) {
            const long r = erow + mi * 16 + half * 8;
            #pragma unroll
            for (int ni = 0; ni < 4; ni++) {
                const int c = ecol + ni * 8;
                float v0 = acc[mi][ni][half * 2 + 0] + bias[c];
                float v1 = acc[mi][ni][half * 2 + 1] + bias[c + 1];
                if (EPI == 2) {
                    v0 = 0.5f * v0 * (1.0f + erff(v0 * 0.70710678118654752f));
                    v1 = 0.5f * v1 * (1.0f + erff(v1 * 0.70710678118654752f));
                }
                if (EPI == 1) {
                    v0 += res[r * N + c];
                    v1 += res[r * N + c + 1];
                }
                float2 o2 = make_float2(v0, v1);
                *(float2*)(C + r * N + c) = o2;
            }
        }
    }
}

// ---------------- Flash attention, fp32 (unchanged) -------------------------
#define ATT_BM 64
#define ATT_BN 64
#define SPAD   100
#define SSTR   65
#define ATT_SMEM ((3 * ATT_BM * SPAD + ATT_BM * SSTR) * (int)sizeof(float))

__global__ __launch_bounds__(256)
void attn_kernel(const float* __restrict__ Q, const float* __restrict__ K,
                 const float* __restrict__ V, float* __restrict__ O) {
    extern __shared__ float sm[];
    float* sQ = sm;
    float* sK = sQ + ATT_BM * SPAD;
    float* sV = sK + ATT_BM * SPAD;
    float* sS = sV + ATT_BM * SPAD;

    const int b  = blockIdx.z;
    const int h  = blockIdx.y;
    const int qt = blockIdx.x;
    const int tid = threadIdx.x;
    const int row = tid >> 2;
    const int sub = tid & 3;
    const int ds  = sub * 24;

    const long baseQ  = ((long)(b * SEQ + qt * ATT_BM)) * EMBD + h * HD;
    const long baseKV = ((long)(b * SEQ)) * EMBD + h * HD;

    for (int i = tid; i < ATT_BM * 24; i += 256) {
        int r = i / 24, c4 = i % 24;
        *(float4*)&sQ[r * SPAD + c4 * 4] =
            *(const float4*)(Q + baseQ + (long)r * EMBD + c4 * 4);
    }

    float o[24];
    #pragma unroll
    for (int j = 0; j < 24; j++) o[j] = 0.f;
    float m = -1e30f, l = 0.f;

    for (int kt = 0; kt < SEQ / ATT_BN; kt++) {
        __syncthreads();
        for (int i = tid; i < ATT_BN * 24; i += 256) {
            int r = i / 24, c4 = i % 24;
            const long go = baseKV + (long)(kt * ATT_BN + r) * EMBD + c4 * 4;
            *(float4*)&sK[r * SPAD + c4 * 4] = *(const float4*)(K + go);
            *(float4*)&sV[r * SPAD + c4 * 4] = *(const float4*)(V + go);
        }
        __syncthreads();

        float s[16];
        #pragma unroll
        for (int j = 0; j < 16; j++) s[j] = 0.f;
        #pragma unroll 4
        for (int d4 = 0; d4 < 24; d4++) {
            float4 qv = *(const float4*)&sQ[row * SPAD + d4 * 4];
            #pragma unroll
            for (int j = 0; j < 16; j++) {
                const int c = j * 4 + sub;
                float4 kv = *(const float4*)&sK[c * SPAD + d4 * 4];
                s[j] += qv.x * kv.x + qv.y * kv.y + qv.z * kv.z + qv.w * kv.w;
            }
        }

        float tmax = -1e30f;
        #pragma unroll
        for (int j = 0; j < 16; j++) tmax = fmaxf(tmax, s[j]);
        tmax = fmaxf(tmax, __shfl_xor_sync(0xffffffffu, tmax, 1));
        tmax = fmaxf(tmax, __shfl_xor_sync(0xffffffffu, tmax, 2));
        const float mnew = fmaxf(m, tmax);
        const float corr = __expf(m - mnew);
        float rsum = 0.f;
        #pragma unroll
        for (int j = 0; j < 16; j++) {
            float p = __expf(s[j] - mnew);
            rsum += p;
            sS[row * SSTR + j * 4 + sub] = p;
        }
        rsum += __shfl_xor_sync(0xffffffffu, rsum, 1);
        rsum += __shfl_xor_sync(0xffffffffu, rsum, 2);
        l = l * corr + rsum;
        m = mnew;
        #pragma unroll
        for (int j = 0; j < 24; j++) o[j] *= corr;
        __syncwarp();

        #pragma unroll 4
        for (int k = 0; k < ATT_BN; k++) {
            const float p = sS[row * SSTR + k];
            #pragma unroll
            for (int j4 = 0; j4 < 6; j4++) {
                float4 vv = *(const float4*)&sV[k * SPAD + ds + j4 * 4];
                o[j4 * 4 + 0] += p * vv.x;
                o[j4 * 4 + 1] += p * vv.y;
                o[j4 * 4 + 2] += p * vv.z;
                o[j4 * 4 + 3] += p * vv.w;
            }
        }
        __syncwarp();
    }

    const float scale = 1.0f / (l * 27.712812921102035f);
    #pragma unroll
    for (int j4 = 0; j4 < 6; j4++) {
        float4 out;
        out.x = o[j4 * 4 + 0] * scale;
        out.y = o[j4 * 4 + 1] * scale;
        out.z = o[j4 * 4 + 2] * scale;
        out.w = o[j4 * 4 + 3] * scale;
        *(float4*)(O + baseQ + (long)row * EMBD + ds + j4 * 4) = out;
    }
}

// ---------------- launch ----------------------------------------------------
extern "C" void kernel_launch(void* const* d_in, const int* in_sizes, int n_in,
                              void* d_out, int out_size) {
    const float* x     = (const float*)d_in[0];
    const float* ln1_g = (const float*)d_in[1];
    const float* ln1_b = (const float*)d_in[2];
    const float* wq    = (const float*)d_in[3];
    const float* bq    = (const float*)d_in[4];
    const float* wk    = (const float*)d_in[5];
    const float* bk    = (const float*)d_in[6];
    const float* wv    = (const float*)d_in[7];
    const float* bv    = (const float*)d_in[8];
    const float* wo    = (const float*)d_in[9];
    const float* bo    = (const float*)d_in[10];
    const float* ln2_g = (const float*)d_in[11];
    const float* ln2_b = (const float*)d_in[12];
    const float* w1    = (const float*)d_in[13];
    const float* b1    = (const float*)d_in[14];
    const float* w2    = (const float*)d_in[15];
    const float* b2    = (const float*)d_in[16];

    float *y, *q, *k, *v, *o, *x1, *z, *hbuf;
    cudaGetSymbolAddress((void**)&y,    g_y);
    cudaGetSymbolAddress((void**)&q,    g_q);
    cudaGetSymbolAddress((void**)&k,    g_k);
    cudaGetSymbolAddress((void**)&v,    g_v);
    cudaGetSymbolAddress((void**)&o,    g_o);
    cudaGetSymbolAddress((void**)&x1,   g_x1);
    cudaGetSymbolAddress((void**)&z,    g_z);
    cudaGetSymbolAddress((void**)&hbuf, g_h);

    cudaFuncSetAttribute(attn_kernel,
                         cudaFuncAttributeMaxDynamicSharedMemorySize, ATT_SMEM);
    cudaFuncSetAttribute(gemm_mma<0>,
                         cudaFuncAttributeMaxDynamicSharedMemorySize, GM_SMEM);
    cudaFuncSetAttribute(gemm_mma<1>,
                         cudaFuncAttributeMaxDynamicSharedMemorySize, GM_SMEM);
    cudaFuncSetAttribute(gemm_mma<2>,
                         cudaFuncAttributeMaxDynamicSharedMemorySize, GM_SMEM);

    // LN1
    ln_kernel<<<TOK, 256>>>(x, ln1_g, ln1_b, y);
    // QKV projections (tf32 mma.sync)
    gemm_mma<0><<<dim3(EMBD / 128, TOK / 128), 256, GM_SMEM>>>(y, wq, bq, nullptr, q, TOK, EMBD, EMBD);
    gemm_mma<0><<<dim3(EMBD / 128, TOK / 128), 256, GM_SMEM>>>(y, wk, bk, nullptr, k, TOK, EMBD, EMBD);
    gemm_mma<0><<<dim3(EMBD / 128, TOK / 128), 256, GM_SMEM>>>(y, wv, bv, nullptr, v, TOK, EMBD, EMBD);
    // attention
    attn_kernel<<<dim3(SEQ / ATT_BM, NHEAD, NBATCH), 256, ATT_SMEM>>>(q, k, v, o);
    // output projection + residual
    gemm_mma<1><<<dim3(EMBD / 128, TOK / 128), 256, GM_SMEM>>>(o, wo, bo, x, x1, TOK, EMBD, EMBD);
    // LN2
    ln_kernel<<<TOK, 256>>>(x1, ln2_g, ln2_b, z);
    // FFN
    gemm_mma<2><<<dim3(DFF2 / 128, TOK / 128), 256, GM_SMEM>>>(z, w1, b1, nullptr, hbuf, TOK, DFF2, EMBD);
    gemm_mma<1><<<dim3(EMBD / 128, TOK / 128), 256, GM_SMEM>>>(hbuf, w2, b2, x1, (float*)d_out, TOK, EMBD, DFF2);
}

// round 4
// speedup vs baseline: 3.9286x; 2.6292x over previous
#include <cuda_runtime.h>
#include <math.h>
#include <stdint.h>

#define TOK   8192
#define EMBD  768
#define DFF2  3072
#define NHEAD 8
#define HD    96
#define SEQ   2048
#define NBATCH 4

// ---------------- scratch (device globals: no allocation allowed) ----------
__device__ float g_y [TOK * EMBD];
__device__ float g_q [TOK * EMBD];
__device__ float g_k [TOK * EMBD];
__device__ float g_v [TOK * EMBD];
__device__ float g_o [TOK * EMBD];
__device__ float g_x1[TOK * EMBD];
__device__ float g_z [TOK * EMBD];
__device__ float g_h [TOK * DFF2];

// ---------------- common helpers --------------------------------------------
__device__ __forceinline__ void cpasync16(uint32_t saddr, const void* gaddr) {
    asm volatile("cp.async.cg.shared.global [%0], [%1], 16;" :: "r"(saddr), "l"(gaddr));
}
#define CP_COMMIT() asm volatile("cp.async.commit_group;" ::: "memory")

__device__ __forceinline__ uint32_t smem_u32(const void* p) {
    uint32_t a;
    asm("{ .reg .u64 t; cvta.to.shared.u64 t, %1; cvt.u32.u64 %0, t; }"
        : "=r"(a) : "l"(p));
    return a;
}

__device__ __forceinline__ uint32_t f2tf(float x) {   // round-to-nearest tf32
    uint32_t r;
    asm("cvt.rna.tf32.f32 %0, %1;" : "=r"(r) : "f"(x));
    return r;
}

__device__ __forceinline__ void mma_tf32(float* c, const uint32_t* a, const uint32_t* b) {
    asm volatile(
        "mma.sync.aligned.m16n8k8.row.col.f32.tf32.tf32.f32 "
        "{%0,%1,%2,%3}, {%4,%5,%6,%7}, {%8,%9}, {%0,%1,%2,%3};"
        : "+f"(c[0]), "+f"(c[1]), "+f"(c[2]), "+f"(c[3])
        : "r"(a[0]), "r"(a[1]), "r"(a[2]), "r"(a[3]), "r"(b[0]), "r"(b[1]));
}

// ---------------- LayerNorm --------------------------------------------------
__global__ __launch_bounds__(256)
void ln_kernel(const float* __restrict__ x, const float* __restrict__ g,
               const float* __restrict__ b, float* __restrict__ y) {
    const int row = blockIdx.x;
    const float* xr = x + (long)row * EMBD;
    const int t = threadIdx.x;
    float v0 = xr[t], v1 = xr[t + 256], v2 = xr[t + 512];
    float s  = v0 + v1 + v2;
    float sq = v0 * v0 + v1 * v1 + v2 * v2;
    #pragma unroll
    for (int o = 16; o; o >>= 1) {
        s  += __shfl_xor_sync(0xffffffffu, s,  o);
        sq += __shfl_xor_sync(0xffffffffu, sq, o);
    }
    __shared__ float sbuf[16];
    const int w = t >> 5, l = t & 31;
    if (l == 0) { sbuf[w] = s; sbuf[w + 8] = sq; }
    __syncthreads();
    float ts = 0.f, tsq = 0.f;
    #pragma unroll
    for (int i = 0; i < 8; i++) { ts += sbuf[i]; tsq += sbuf[8 + i]; }
    const float mu  = ts * (1.0f / EMBD);
    const float var = tsq * (1.0f / EMBD) - mu * mu;
    const float r   = rsqrtf(var + 1e-5f);
    float* yr = y + (long)row * EMBD;
    yr[t]       = (v0 - mu) * r * g[t]       + b[t];
    yr[t + 256] = (v1 - mu) * r * g[t + 256] + b[t + 256];
    yr[t + 512] = (v2 - mu) * r * g[t + 512] + b[t + 512];
}

// =================== tf32 mma.sync GEMM: C = A[M,K] @ W[K,N] =================
#define GK        32
#define A_STR     36
#define B_STR     136
#define A_BYTES   (128 * A_STR * 4)
#define B_BYTES   (GK * B_STR * 4)
#define STG_BYTES (A_BYTES + B_BYTES)
#define GM_SMEM   (2 * STG_BYTES)

__device__ __forceinline__ void ld_stage(uint32_t sa, uint32_t sb,
                                         const float* __restrict__ A,
                                         const float* __restrict__ W,
                                         int bm, int bn, int K, int N, int k0,
                                         int tid) {
    #pragma unroll
    for (int j = 0; j < 4; j++) {
        const int ch = tid + j * 256;
        const int m = ch >> 3, k4 = ch & 7;
        cpasync16(sa + (m * A_STR + k4 * 4) * 4,
                  A + (long)(bm + m) * K + k0 + k4 * 4);
    }
    #pragma unroll
    for (int j = 0; j < 4; j++) {
        const int ch = tid + j * 256;
        const int r = ch >> 5, c = ch & 31;
        cpasync16(sb + (r * B_STR + c * 4) * 4,
                  W + (long)(k0 + r) * N + bn + c * 4);
    }
}

template <int EPI>
__global__ __launch_bounds__(256, 1)
void gemm_mma(const float* __restrict__ A, const float* __restrict__ W,
              const float* __restrict__ bias, const float* __restrict__ res,
              float* __restrict__ C, int M, int N, int K) {
    extern __shared__ float smf[];
    const uint32_t sbase = smem_u32(smf);

    const int tid  = threadIdx.x;
    const int lane = tid & 31;
    const int wid  = tid >> 5;
    const int bm = blockIdx.y * 128;
    const int bn = blockIdx.x * 128;
    const int wm = (wid & 1) * 64;
    const int wn = (wid >> 1) * 32;

    const int rA = wm + (lane >> 2);
    const int cA = lane & 3;
    const int nB = wn + (lane >> 2);

    float acc[4][4][4];
    #pragma unroll
    for (int mi = 0; mi < 4; mi++)
        #pragma unroll
        for (int ni = 0; ni < 4; ni++)
            #pragma unroll
            for (int u = 0; u < 4; u++) acc[mi][ni][u] = 0.f;

    const int nkt = K / GK;
    ld_stage(sbase, sbase + A_BYTES, A, W, bm, bn, K, N, 0, tid);
    CP_COMMIT();

    for (int kt = 0; kt < nkt; kt++) {
        const float* fA = (const float*)(smf) + (kt & 1) * (STG_BYTES / 4);
        const float* fB = fA + A_BYTES / 4;

        if (kt + 1 < nkt) {
            const uint32_t sn = sbase + ((kt + 1) & 1) * STG_BYTES;
            ld_stage(sn, sn + A_BYTES, A, W, bm, bn, K, N, (kt + 1) * GK, tid);
            CP_COMMIT();
            asm volatile("cp.async.wait_group 1;" ::: "memory");
        } else {
            asm volatile("cp.async.wait_group 0;" ::: "memory");
        }
        __syncthreads();

        #pragma unroll
        for (int ks = 0; ks < 4; ks++) {
            uint32_t af[4][4];
            #pragma unroll
            for (int mi = 0; mi < 4; mi++) {
                const float* p = fA + (rA + mi * 16) * A_STR + ks * 8 + cA;
                af[mi][0] = f2tf(p[0]);
                af[mi][1] = f2tf(p[8 * A_STR]);
                af[mi][2] = f2tf(p[4]);
                af[mi][3] = f2tf(p[8 * A_STR + 4]);
            }
            uint32_t bf[4][2];
            #pragma unroll
            for (int ni = 0; ni < 4; ni++) {
                const float* p = fB + (ks * 8 + cA) * B_STR + nB + ni * 8;
                bf[ni][0] = f2tf(p[0]);
                bf[ni][1] = f2tf(p[4 * B_STR]);
            }
            #pragma unroll
            for (int mi = 0; mi < 4; mi++)
                #pragma unroll
                for (int ni = 0; ni < 4; ni++)
                    mma_tf32(acc[mi][ni], af[mi], bf[ni]);
        }
        __syncthreads();
    }

    const int erow = bm + wm + (lane >> 2);
    const int ecol = bn + wn + (lane & 3) * 2;
    #pragma unroll
    for (int mi = 0; mi < 4; mi++) {
        #pragma unroll
        for (int half = 0; half < 2; half++) {
            const long r = erow + mi * 16 + half * 8;
            #pragma unroll
            for (int ni = 0; ni < 4; ni++) {
                const int c = ecol + ni * 8;
                float v0 = acc[mi][ni][half * 2 + 0] + bias[c];
                float v1 = acc[mi][ni][half * 2 + 1] + bias[c + 1];
                if (EPI == 2) {
                    v0 = 0.5f * v0 * (1.0f + erff(v0 * 0.70710678118654752f));
                    v1 = 0.5f * v1 * (1.0f + erff(v1 * 0.70710678118654752f));
                }
                if (EPI == 1) {
                    v0 += res[r * N + c];
                    v1 += res[r * N + c + 1];
                }
                *(float2*)(C + r * N + c) = make_float2(v0, v1);
            }
        }
    }
}

// =================== tf32 flash attention ===================================
// O = (1/sqrt(768)) * softmax(Q K^T) V ; softmax scale = 1 (ref divides after).
#define FBM   128            // q rows per CTA
#define FBN   64             // kv per iteration
#define QSTR  100            // sQ row stride  (== 4 mod 32)
#define KSTR  100            // sK row stride  (== 4 mod 32)
#define VSTR  104            // sV row stride  (== 8 mod 32)
#define SSTR  68             // sS row stride  (== 4 mod 32)
#define SQ_F   (FBM * QSTR)
#define SS_F   (FBM * SSTR)
#define KV_F   (FBN * (KSTR + VSTR))
#define ATT_SMEM ((SQ_F + SS_F + 2 * KV_F) * (int)sizeof(float))

__device__ __forceinline__ void attn_ld_kv(uint32_t sk, uint32_t sv,
                                           const float* __restrict__ K,
                                           const float* __restrict__ V,
                                           long baseKV, int kt, int tid) {
    const long g0 = baseKV + (long)(kt * FBN) * EMBD;
    #pragma unroll
    for (int j = 0; j < 6; j++) {
        const int i = tid + j * 256;           // 0..1535
        const int r = i / 24, c = i % 24;
        const long go = g0 + (long)r * EMBD + c * 4;
        cpasync16(sk + (r * KSTR + c * 4) * 4, K + go);
        cpasync16(sv + (r * VSTR + c * 4) * 4, V + go);
    }
}

__global__ __launch_bounds__(256, 1)
void attn_tc(const float* __restrict__ Q, const float* __restrict__ K,
             const float* __restrict__ V, float* __restrict__ O) {
    extern __shared__ float sm[];
    float* sQ = sm;
    float* sS = sQ + SQ_F;
    float* sKV = sS + SS_F;                     // [stage][K 64*KSTR | V 64*VSTR]
    const uint32_t skv_u = smem_u32(sKV);

    const int b  = blockIdx.z;
    const int h  = blockIdx.y;
    const int qt = blockIdx.x;
    const int tid  = threadIdx.x;
    const int lane = tid & 31;
    const int wid  = tid >> 5;

    const long baseQ  = ((long)(b * SEQ + qt * FBM)) * EMBD + h * HD;
    const long baseKV = ((long)(b * SEQ)) * EMBD + h * HD;

    // load Q tile (128 x 96)
    for (int i = tid; i < FBM * 24; i += 256) {
        const int r = i / 24, c = i % 24;
        *(float4*)&sQ[r * QSTR + c * 4] =
            *(const float4*)(Q + baseQ + (long)r * EMBD + c * 4);
    }

    // prefetch stage 0
    attn_ld_kv(skv_u, skv_u + FBN * KSTR * 4, K, V, baseKV, 0, tid);
    CP_COMMIT();

    const int rA = wid * 16 + (lane >> 2);     // q row (this warp: 16 rows)
    const int cA = lane & 3;
    const int nB = lane >> 2;

    float m0 = -1e30f, m1 = -1e30f, l0 = 0.f, l1 = 0.f;
    float oa[12][4];
    #pragma unroll
    for (int nf = 0; nf < 12; nf++)
        #pragma unroll
        for (int u = 0; u < 4; u++) oa[nf][u] = 0.f;

    const int NIT = SEQ / FBN;                  // 32
    for (int it = 0; it < NIT; it++) {
        const int st = it & 1;
        const float* fK = sKV + st * KV_F;
        const float* fV = fK + FBN * KSTR;

        __syncthreads();                         // prev compute done
        if (it + 1 < NIT) {
            const uint32_t sn = skv_u + ((it + 1) & 1) * KV_F * 4;
            attn_ld_kv(sn, sn + FBN * KSTR * 4, K, V, baseKV, it + 1, tid);
            CP_COMMIT();
            asm volatile("cp.async.wait_group 1;" ::: "memory");
        } else {
            asm volatile("cp.async.wait_group 0;" ::: "memory");
        }
        __syncthreads();                         // current stage visible

        // ---- S = Q K^T (16 x 64 per warp) ----
        float sc[8][4];
        #pragma unroll
        for (int nf = 0; nf < 8; nf++)
            #pragma unroll
            for (int u = 0; u < 4; u++) sc[nf][u] = 0.f;

        #pragma unroll
        for (int ks = 0; ks < 12; ks++) {
            uint32_t af[4];
            const float* pa = sQ + rA * QSTR + ks * 8 + cA;
            af[0] = f2tf(pa[0]);
            af[1] = f2tf(pa[8 * QSTR]);
            af[2] = f2tf(pa[4]);
            af[3] = f2tf(pa[8 * QSTR + 4]);
            #pragma unroll
            for (int nf = 0; nf < 8; nf++) {
                uint32_t bf[2];
                const float* pb = fK + (nf * 8 + nB) * KSTR + ks * 8 + cA;
                bf[0] = f2tf(pb[0]);
                bf[1] = f2tf(pb[4]);
                mma_tf32(sc[nf], af, bf);
            }
        }

        // ---- online softmax (rows rA and rA+8) ----
        float t0 = -1e30f, t1 = -1e30f;
        #pragma unroll
        for (int nf = 0; nf < 8; nf++) {
            t0 = fmaxf(t0, fmaxf(sc[nf][0], sc[nf][1]));
            t1 = fmaxf(t1, fmaxf(sc[nf][2], sc[nf][3]));
        }
        t0 = fmaxf(t0, __shfl_xor_sync(0xffffffffu, t0, 1));
        t0 = fmaxf(t0, __shfl_xor_sync(0xffffffffu, t0, 2));
        t1 = fmaxf(t1, __shfl_xor_sync(0xffffffffu, t1, 1));
        t1 = fmaxf(t1, __shfl_xor_sync(0xffffffffu, t1, 2));
        const float mn0 = fmaxf(m0, t0), mn1 = fmaxf(m1, t1);
        const float cr0 = __expf(m0 - mn0), cr1 = __expf(m1 - mn1);
        float rs0 = 0.f, rs1 = 0.f;
        #pragma unroll
        for (int nf = 0; nf < 8; nf++) {
            const float p00 = __expf(sc[nf][0] - mn0);
            const float p01 = __expf(sc[nf][1] - mn0);
            const float p10 = __expf(sc[nf][2] - mn1);
            const float p11 = __expf(sc[nf][3] - mn1);
            rs0 += p00 + p01; rs1 += p10 + p11;
            const int col = nf * 8 + (lane & 3) * 2;
            *(float2*)&sS[rA * SSTR + col]       = make_float2(p00, p01);
            *(float2*)&sS[(rA + 8) * SSTR + col] = make_float2(p10, p11);
        }
        rs0 += __shfl_xor_sync(0xffffffffu, rs0, 1);
        rs0 += __shfl_xor_sync(0xffffffffu, rs0, 2);
        rs1 += __shfl_xor_sync(0xffffffffu, rs1, 1);
        rs1 += __shfl_xor_sync(0xffffffffu, rs1, 2);
        l0 = l0 * cr0 + rs0; m0 = mn0;
        l1 = l1 * cr1 + rs1; m1 = mn1;
        #pragma unroll
        for (int nf = 0; nf < 12; nf++) {
            oa[nf][0] *= cr0; oa[nf][1] *= cr0;
            oa[nf][2] *= cr1; oa[nf][3] *= cr1;
        }
        __syncwarp();   // sS rows are warp-private

        // ---- O += P V (16 x 96 per warp) ----
        #pragma unroll
        for (int ks = 0; ks < 8; ks++) {
            uint32_t af[4];
            const float* pa = sS + rA * SSTR + ks * 8 + cA;
            af[0] = f2tf(pa[0]);
            af[1] = f2tf(pa[8 * SSTR]);
            af[2] = f2tf(pa[4]);
            af[3] = f2tf(pa[8 * SSTR + 4]);
            #pragma unroll
            for (int nf = 0; nf < 12; nf++) {
                uint32_t bf[2];
                const float* pb = fV + (ks * 8 + cA) * VSTR + nf * 8 + nB;
                bf[0] = f2tf(pb[0]);
                bf[1] = f2tf(pb[4 * VSTR]);
                mma_tf32(oa[nf], af, bf);
            }
        }
        __syncwarp();
    }

    const float s0 = 1.0f / (l0 * 27.712812921102035f);
    const float s1 = 1.0f / (l1 * 27.712812921102035f);
    #pragma unroll
    for (int nf = 0; nf < 12; nf++) {
        const int col = nf * 8 + (lane & 3) * 2;
        *(float2*)(O + baseQ + (long)rA * EMBD + col) =
            make_float2(oa[nf][0] * s0, oa[nf][1] * s0);
        *(float2*)(O + baseQ + (long)(rA + 8) * EMBD + col) =
            make_float2(oa[nf][2] * s1, oa[nf][3] * s1);
    }
}

// ---------------- launch ----------------------------------------------------
extern "C" void kernel_launch(void* const* d_in, const int* in_sizes, int n_in,
                              void* d_out, int out_size) {
    const float* x     = (const float*)d_in[0];
    const float* ln1_g = (const float*)d_in[1];
    const float* ln1_b = (const float*)d_in[2];
    const float* wq    = (const float*)d_in[3];
    const float* bq    = (const float*)d_in[4];
    const float* wk    = (const float*)d_in[5];
    const float* bk    = (const float*)d_in[6];
    const float* wv    = (const float*)d_in[7];
    const float* bv    = (const float*)d_in[8];
    const float* wo    = (const float*)d_in[9];
    const float* bo    = (const float*)d_in[10];
    const float* ln2_g = (const float*)d_in[11];
    const float* ln2_b = (const float*)d_in[12];
    const float* w1    = (const float*)d_in[13];
    const float* b1    = (const float*)d_in[14];
    const float* w2    = (const float*)d_in[15];
    const float* b2    = (const float*)d_in[16];

    float *y, *q, *k, *v, *o, *x1, *z, *hbuf;
    cudaGetSymbolAddress((void**)&y,    g_y);
    cudaGetSymbolAddress((void**)&q,    g_q);
    cudaGetSymbolAddress((void**)&k,    g_k);
    cudaGetSymbolAddress((void**)&v,    g_v);
    cudaGetSymbolAddress((void**)&o,    g_o);
    cudaGetSymbolAddress((void**)&x1,   g_x1);
    cudaGetSymbolAddress((void**)&z,    g_z);
    cudaGetSymbolAddress((void**)&hbuf, g_h);

    cudaFuncSetAttribute(attn_tc,
                         cudaFuncAttributeMaxDynamicSharedMemorySize, ATT_SMEM);
    cudaFuncSetAttribute(gemm_mma<0>,
                         cudaFuncAttributeMaxDynamicSharedMemorySize, GM_SMEM);
    cudaFuncSetAttribute(gemm_mma<1>,
                         cudaFuncAttributeMaxDynamicSharedMemorySize, GM_SMEM);
    cudaFuncSetAttribute(gemm_mma<2>,
                         cudaFuncAttributeMaxDynamicSharedMemorySize, GM_SMEM);

    // LN1
    ln_kernel<<<TOK, 256>>>(x, ln1_g, ln1_b, y);
    // QKV projections (tf32 mma.sync)
    gemm_mma<0><<<dim3(EMBD / 128, TOK / 128), 256, GM_SMEM>>>(y, wq, bq, nullptr, q, TOK, EMBD, EMBD);
    gemm_mma<0><<<dim3(EMBD / 128, TOK / 128), 256, GM_SMEM>>>(y, wk, bk, nullptr, k, TOK, EMBD, EMBD);
    gemm_mma<0><<<dim3(EMBD / 128, TOK / 128), 256, GM_SMEM>>>(y, wv, bv, nullptr, v, TOK, EMBD, EMBD);
    // attention (tf32 mma.sync flash)
    attn_tc<<<dim3(SEQ / FBM, NHEAD, NBATCH), 256, ATT_SMEM>>>(q, k, v, o);
    // output projection + residual
    gemm_mma<1><<<dim3(EMBD / 128, TOK / 128), 256, GM_SMEM>>>(o, wo, bo, x, x1, TOK, EMBD, EMBD);
    // LN2
    ln_kernel<<<TOK, 256>>>(x1, ln2_g, ln2_b, z);
    // FFN
    gemm_mma<2><<<dim3(DFF2 / 128, TOK / 128), 256, GM_SMEM>>>(z, w1, b1, nullptr, hbuf, TOK, DFF2, EMBD);
    gemm_mma<1><<<dim3(EMBD / 128, TOK / 128), 256, GM_SMEM>>>(hbuf, w2, b2, x1, (float*)d_out, TOK, EMBD, DFF2);
}

// round 5
// speedup vs baseline: 7.2516x; 1.8459x over previous
#include <cuda_runtime.h>
#include <cuda_fp16.h>
#include <math.h>
#include <stdint.h>

#define TOK   8192
#define EMBD  768
#define DFF2  3072
#define NHEAD 8
#define HD    96
#define SEQ   2048
#define NBATCH 4

// ---------------- scratch (device globals) ----------------------------------
__device__ __half g_yh[TOK * EMBD];
__device__ __half g_qh[TOK * EMBD];
__device__ __half g_kh[TOK * EMBD];
__device__ __half g_vT[TOK * EMBD];     // [b][h][d][seq]
__device__ __half g_oh[TOK * EMBD];
__device__ __half g_zh[TOK * EMBD];
__device__ __half g_hh[TOK * DFF2];
__device__ float  g_x1[TOK * EMBD];
// fp16 transposed weights [N][K]
__device__ __half g_wqT[EMBD * EMBD];
__device__ __half g_wkT[EMBD * EMBD];
__device__ __half g_wvT[EMBD * EMBD];
__device__ __half g_woT[EMBD * EMBD];
__device__ __half g_w1T[DFF2 * EMBD];
__device__ __half g_w2T[EMBD * DFF2];

// ---------------- helpers ----------------------------------------------------
__device__ __forceinline__ void cpasync16(uint32_t saddr, const void* gaddr) {
    asm volatile("cp.async.cg.shared.global [%0], [%1], 16;" :: "r"(saddr), "l"(gaddr));
}
#define CP_COMMIT() asm volatile("cp.async.commit_group;" ::: "memory")

__device__ __forceinline__ uint32_t smem_u32(const void* p) {
    uint32_t a;
    asm("{ .reg .u64 t; cvta.to.shared.u64 t, %1; cvt.u32.u64 %0, t; }"
        : "=r"(a) : "l"(p));
    return a;
}

__device__ __forceinline__ void mma_f16(float* c, const uint32_t* a, const uint32_t* b) {
    asm volatile(
        "mma.sync.aligned.m16n8k16.row.col.f32.f16.f16.f32 "
        "{%0,%1,%2,%3}, {%4,%5,%6,%7}, {%8,%9}, {%0,%1,%2,%3};"
        : "+f"(c[0]), "+f"(c[1]), "+f"(c[2]), "+f"(c[3])
        : "r"(a[0]), "r"(a[1]), "r"(a[2]), "r"(a[3]), "r"(b[0]), "r"(b[1]));
}

__device__ __forceinline__ uint32_t ldu32(const __half* p) {
    return *(const uint32_t*)p;
}

// ---------------- weight convert+transpose: Wt[n][k] = (half)W[k][n] --------
__global__ __launch_bounds__(256)
void convT_kernel(const float* __restrict__ W, __half* __restrict__ Wt,
                  int K, int N) {
    __shared__ float t[32][33];
    const int n0 = blockIdx.x * 32, k0 = blockIdx.y * 32;
    const int tx = threadIdx.x, ty = threadIdx.y;   // 32 x 8
    #pragma unroll
    for (int i = 0; i < 32; i += 8)
        t[ty + i][tx] = W[(long)(k0 + ty + i) * N + n0 + tx];
    __syncthreads();
    #pragma unroll
    for (int i = 0; i < 32; i += 8)
        Wt[(long)(n0 + ty + i) * K + k0 + tx] = __float2half(t[tx][ty + i]);
}

// ---------------- LayerNorm (fp32 in -> fp16 out) ---------------------------
__global__ __launch_bounds__(256)
void ln_kernel(const float* __restrict__ x, const float* __restrict__ g,
               const float* __restrict__ b, __half* __restrict__ y) {
    const int row = blockIdx.x;
    const float* xr = x + (long)row * EMBD;
    const int t = threadIdx.x;
    float v0 = xr[t], v1 = xr[t + 256], v2 = xr[t + 512];
    float s  = v0 + v1 + v2;
    float sq = v0 * v0 + v1 * v1 + v2 * v2;
    #pragma unroll
    for (int o = 16; o; o >>= 1) {
        s  += __shfl_xor_sync(0xffffffffu, s,  o);
        sq += __shfl_xor_sync(0xffffffffu, sq, o);
    }
    __shared__ float sbuf[16];
    const int w = t >> 5, l = t & 31;
    if (l == 0) { sbuf[w] = s; sbuf[w + 8] = sq; }
    __syncthreads();
    float ts = 0.f, tsq = 0.f;
    #pragma unroll
    for (int i = 0; i < 8; i++) { ts += sbuf[i]; tsq += sbuf[8 + i]; }
    const float mu  = ts * (1.0f / EMBD);
    const float var = tsq * (1.0f / EMBD) - mu * mu;
    const float r   = rsqrtf(var + 1e-5f);
    __half* yr = y + (long)row * EMBD;
    yr[t]       = __float2half((v0 - mu) * r * g[t]       + b[t]);
    yr[t + 256] = __float2half((v1 - mu) * r * g[t + 256] + b[t + 256]);
    yr[t + 512] = __float2half((v2 - mu) * r * g[t + 512] + b[t + 512]);
}

// ============ fp16 mma GEMM: C = A[M,K](h) @ Bt[N,K](h)^T + epi ==============
// EPI: 0 bias, 1 bias+res(fp32), 2 bias+GELU. OUTH: fp16 out. TRV: V-transpose out.
#define HGK    64                        // K per stage
#define HSTR   72                        // smem row stride (halves); /2 == 36 == 4 mod 8
#define OP_BYTES (128 * HSTR * 2)        // 18432 per operand
#define HSTG   (2 * OP_BYTES)            // 36864
#define GMH_SMEM (2 * HSTG)              // 73728

__device__ __forceinline__ void ld_stage_h(uint32_t sa, uint32_t sb,
                                           const __half* __restrict__ A,
                                           const __half* __restrict__ Bt,
                                           int bm, int bn, int KA, int KB,
                                           int k0, int tid) {
    #pragma unroll
    for (int j = 0; j < 4; j++) {
        const int ch = tid + j * 256;    // 0..1023
        const int r = ch >> 3, kc = ch & 7;
        cpasync16(sa + (r * HSTR + kc * 8) * 2,
                  A + (long)(bm + r) * KA + k0 + kc * 8);
    }
    #pragma unroll
    for (int j = 0; j < 4; j++) {
        const int ch = tid + j * 256;
        const int r = ch >> 3, kc = ch & 7;
        cpasync16(sb + (r * HSTR + kc * 8) * 2,
                  Bt + (long)(bn + r) * KB + k0 + kc * 8);
    }
}

template <int EPI, int OUTH, int TRV>
__global__ __launch_bounds__(256, 1)
void gemm_h(const __half* __restrict__ A, const __half* __restrict__ Bt,
            const float* __restrict__ bias, const float* __restrict__ res,
            void* __restrict__ Cout, int M, int N, int K) {
    extern __shared__ __half smh[];
    const uint32_t sbase = smem_u32(smh);

    const int tid  = threadIdx.x;
    const int lane = tid & 31;
    const int wid  = tid >> 5;
    const int bm = blockIdx.y * 128;
    const int bn = blockIdx.x * 128;
    const int wm = (wid & 1) * 64;
    const int wn = (wid >> 1) * 32;

    const int rA = wm + (lane >> 2);
    const int cA = lane & 3;
    const int nB = wn + (lane >> 2);

    float acc[4][4][4];
    #pragma unroll
    for (int mi = 0; mi < 4; mi++)
        #pragma unroll
        for (int ni = 0; ni < 4; ni++)
            #pragma unroll
            for (int u = 0; u < 4; u++) acc[mi][ni][u] = 0.f;

    const int nkt = K / HGK;
    ld_stage_h(sbase, sbase + OP_BYTES, A, Bt, bm, bn, K, K, 0, tid);
    CP_COMMIT();

    for (int kt = 0; kt < nkt; kt++) {
        const __half* fA = smh + (kt & 1) * (HSTG / 2);
        const __half* fB = fA + OP_BYTES / 2;

        if (kt + 1 < nkt) {
            const uint32_t sn = sbase + ((kt + 1) & 1) * HSTG;
            ld_stage_h(sn, sn + OP_BYTES, A, Bt, bm, bn, K, K, (kt + 1) * HGK, tid);
            CP_COMMIT();
            asm volatile("cp.async.wait_group 1;" ::: "memory");
        } else {
            asm volatile("cp.async.wait_group 0;" ::: "memory");
        }
        __syncthreads();

        #pragma unroll
        for (int ks = 0; ks < 4; ks++) {
            uint32_t af[4][4];
            #pragma unroll
            for (int mi = 0; mi < 4; mi++) {
                const __half* p = fA + (rA + mi * 16) * HSTR + ks * 16 + 2 * cA;
                af[mi][0] = ldu32(p);
                af[mi][1] = ldu32(p + 8 * HSTR);
                af[mi][2] = ldu32(p + 8);
                af[mi][3] = ldu32(p + 8 * HSTR + 8);
            }
            uint32_t bf[4][2];
            #pragma unroll
            for (int ni = 0; ni < 4; ni++) {
                const __half* p = fB + (nB + ni * 8) * HSTR + ks * 16 + 2 * cA;
                bf[ni][0] = ldu32(p);
                bf[ni][1] = ldu32(p + 8);
            }
            #pragma unroll
            for (int mi = 0; mi < 4; mi++)
                #pragma unroll
                for (int ni = 0; ni < 4; ni++)
                    mma_f16(acc[mi][ni], af[mi], bf[ni]);
        }
        __syncthreads();
    }

    const int erow = bm + wm + (lane >> 2);
    const int ecol = bn + wn + (lane & 3) * 2;
    #pragma unroll
    for (int mi = 0; mi < 4; mi++) {
        #pragma unroll
        for (int half = 0; half < 2; half++) {
            const long r = erow + mi * 16 + half * 8;
            #pragma unroll
            for (int ni = 0; ni < 4; ni++) {
                const int c = ecol + ni * 8;
                float v0 = acc[mi][ni][half * 2 + 0] + bias[c];
                float v1 = acc[mi][ni][half * 2 + 1] + bias[c + 1];
                if (EPI == 2) {
                    v0 = 0.5f * v0 * (1.0f + erff(v0 * 0.70710678118654752f));
                    v1 = 0.5f * v1 * (1.0f + erff(v1 * 0.70710678118654752f));
                }
                if (EPI == 1) {
                    v0 += res[r * N + c];
                    v1 += res[r * N + c + 1];
                }
                if (TRV) {
                    // vT[b][h][d][s]; r = b*SEQ+s, c = h*96+d
                    const int bb = (int)(r >> 11), sidx = (int)(r & 2047);
                    __half* vt = (__half*)Cout;
                    const long o0 = ((long)(bb * NHEAD + c / HD) * HD + (c % HD)) * SEQ + sidx;
                    const long o1 = ((long)(bb * NHEAD + (c + 1) / HD) * HD + ((c + 1) % HD)) * SEQ + sidx;
                    vt[o0] = __float2half(v0);
                    vt[o1] = __float2half(v1);
                } else if (OUTH) {
                    *(__half2*)((__half*)Cout + r * N + c) = __floats2half2_rn(v0, v1);
                } else {
                    *(float2*)((float*)Cout + r * N + c) = make_float2(v0, v1);
                }
            }
        }
    }
}

// =================== fp16 flash attention ===================================
#define FBM    128
#define FBN    64
#define QSTR_H 104     // /2 == 52 == 4 mod 8
#define KSTR_H 104
#define VSTR_H 72      // vT rows: 64 kv + pad
#define PSTR_H 72
#define SQ_H   (FBM * QSTR_H)
#define SP_H   (FBM * PSTR_H)
#define KV_H   (FBN * KSTR_H + HD * VSTR_H)
#define ATT_SMEM ((SQ_H + SP_H + 2 * KV_H) * 2)

__device__ __forceinline__ void attn_ld_kv_h(uint32_t sk, uint32_t sv,
                                             const __half* __restrict__ K,
                                             const __half* __restrict__ VT,
                                             long baseKV, long baseVT,
                                             int kt, int tid) {
    #pragma unroll
    for (int j = 0; j < 3; j++) {            // K tile: 64 rows x 12 chunks
        const int ch = tid + j * 256;        // 0..767
        const int r = ch / 12, c = ch % 12;
        cpasync16(sk + (r * KSTR_H + c * 8) * 2,
                  K + baseKV + (long)(kt * FBN + r) * EMBD + c * 8);
    }
    #pragma unroll
    for (int j = 0; j < 3; j++) {            // vT tile: 96 rows x 8 chunks
        const int ch = tid + j * 256;
        const int d = ch >> 3, sc = ch & 7;
        cpasync16(sv + (d * VSTR_H + sc * 8) * 2,
                  VT + baseVT + (long)d * SEQ + kt * FBN + sc * 8);
    }
}

__global__ __launch_bounds__(256, 1)
void attn_h(const __half* __restrict__ Q, const __half* __restrict__ K,
            const __half* __restrict__ VT, __half* __restrict__ O) {
    extern __shared__ __half smh[];
    __half* sQ = smh;
    __half* sP = sQ + SQ_H;
    __half* sKV = sP + SP_H;
    const uint32_t skv_u = smem_u32(sKV);

    const int b  = blockIdx.z;
    const int h  = blockIdx.y;
    const int qt = blockIdx.x;
    const int tid  = threadIdx.x;
    const int lane = tid & 31;
    const int wid  = tid >> 5;

    const long baseQ  = ((long)(b * SEQ + qt * FBM)) * EMBD + h * HD;
    const long baseKV = ((long)(b * SEQ)) * EMBD + h * HD;
    const long baseVT = (long)(b * NHEAD + h) * HD * SEQ;

    for (int i = tid; i < FBM * 12; i += 256) {       // Q: 128 x 96 halves
        const int r = i / 12, c = i % 12;
        cpasync16(smem_u32(sQ) + (r * QSTR_H + c * 8) * 2,
                  Q + baseQ + (long)r * EMBD + c * 8);
    }
    attn_ld_kv_h(skv_u, skv_u + FBN * KSTR_H * 2, K, VT, baseKV, baseVT, 0, tid);
    CP_COMMIT();

    const int rA = wid * 16 + (lane >> 2);
    const int cA = lane & 3;
    const int nB = lane >> 2;

    float m0 = -1e30f, m1 = -1e30f, l0 = 0.f, l1 = 0.f;
    float oa[12][4];
    #pragma unroll
    for (int nf = 0; nf < 12; nf++)
        #pragma unroll
        for (int u = 0; u < 4; u++) oa[nf][u] = 0.f;

    const int NIT = SEQ / FBN;
    for (int it = 0; it < NIT; it++) {
        const __half* fK = sKV + (it & 1) * KV_H;
        const __half* fV = fK + FBN * KSTR_H;

        __syncthreads();
        if (it + 1 < NIT) {
            const uint32_t sn = skv_u + ((it + 1) & 1) * KV_H * 2;
            attn_ld_kv_h(sn, sn + FBN * KSTR_H * 2, K, VT, baseKV, baseVT, it + 1, tid);
            CP_COMMIT();
            asm volatile("cp.async.wait_group 1;" ::: "memory");
        } else {
            asm volatile("cp.async.wait_group 0;" ::: "memory");
        }
        __syncthreads();

        // ---- S = Q K^T ----
        float sc[8][4];
        #pragma unroll
        for (int nf = 0; nf < 8; nf++)
            #pragma unroll
            for (int u = 0; u < 4; u++) sc[nf][u] = 0.f;

        #pragma unroll
        for (int ks = 0; ks < 6; ks++) {
            uint32_t af[4];
            const __half* pa = sQ + rA * QSTR_H + ks * 16 + 2 * cA;
            af[0] = ldu32(pa);
            af[1] = ldu32(pa + 8 * QSTR_H);
            af[2] = ldu32(pa + 8);
            af[3] = ldu32(pa + 8 * QSTR_H + 8);
            #pragma unroll
            for (int nf = 0; nf < 8; nf++) {
                uint32_t bf[2];
                const __half* pb = fK + (nf * 8 + nB) * KSTR_H + ks * 16 + 2 * cA;
                bf[0] = ldu32(pb);
                bf[1] = ldu32(pb + 8);
                mma_f16(sc[nf], af, bf);
            }
        }

        // ---- online softmax ----
        float t0 = -1e30f, t1 = -1e30f;
        #pragma unroll
        for (int nf = 0; nf < 8; nf++) {
            t0 = fmaxf(t0, fmaxf(sc[nf][0], sc[nf][1]));
            t1 = fmaxf(t1, fmaxf(sc[nf][2], sc[nf][3]));
        }
        t0 = fmaxf(t0, __shfl_xor_sync(0xffffffffu, t0, 1));
        t0 = fmaxf(t0, __shfl_xor_sync(0xffffffffu, t0, 2));
        t1 = fmaxf(t1, __shfl_xor_sync(0xffffffffu, t1, 1));
        t1 = fmaxf(t1, __shfl_xor_sync(0xffffffffu, t1, 2));
        const float mn0 = fmaxf(m0, t0), mn1 = fmaxf(m1, t1);
        const float cr0 = __expf(m0 - mn0), cr1 = __expf(m1 - mn1);
        float rs0 = 0.f, rs1 = 0.f;
        #pragma unroll
        for (int nf = 0; nf < 8; nf++) {
            const float p00 = __expf(sc[nf][0] - mn0);
            const float p01 = __expf(sc[nf][1] - mn0);
            const float p10 = __expf(sc[nf][2] - mn1);
            const float p11 = __expf(sc[nf][3] - mn1);
            rs0 += p00 + p01; rs1 += p10 + p11;
            const int col = nf * 8 + (lane & 3) * 2;
            *(__half2*)&sP[rA * PSTR_H + col]       = __floats2half2_rn(p00, p01);
            *(__half2*)&sP[(rA + 8) * PSTR_H + col] = __floats2half2_rn(p10, p11);
        }
        rs0 += __shfl_xor_sync(0xffffffffu, rs0, 1);
        rs0 += __shfl_xor_sync(0xffffffffu, rs0, 2);
        rs1 += __shfl_xor_sync(0xffffffffu, rs1, 1);
        rs1 += __shfl_xor_sync(0xffffffffu, rs1, 2);
        l0 = l0 * cr0 + rs0; m0 = mn0;
        l1 = l1 * cr1 + rs1; m1 = mn1;
        #pragma unroll
        for (int nf = 0; nf < 12; nf++) {
            oa[nf][0] *= cr0; oa[nf][1] *= cr0;
            oa[nf][2] *= cr1; oa[nf][3] *= cr1;
        }
        __syncwarp();

        // ---- O += P V  (B = vT[d][kv]) ----
        #pragma unroll
        for (int ks = 0; ks < 4; ks++) {
            uint32_t af[4];
            const __half* pa = sP + rA * PSTR_H + ks * 16 + 2 * cA;
            af[0] = ldu32(pa);
            af[1] = ldu32(pa + 8 * PSTR_H);
            af[2] = ldu32(pa + 8);
            af[3] = ldu32(pa + 8 * PSTR_H + 8);
            #pragma unroll
            for (int nf = 0; nf < 12; nf++) {
                uint32_t bf[2];
                const __half* pb = fV + (nf * 8 + nB) * VSTR_H + ks * 16 + 2 * cA;
                bf[0] = ldu32(pb);
                bf[1] = ldu32(pb + 8);
                mma_f16(oa[nf], af, bf);
            }
        }
        __syncwarp();
    }

    const float s0 = 1.0f / (l0 * 27.712812921102035f);
    const float s1 = 1.0f / (l1 * 27.712812921102035f);
    #pragma unroll
    for (int nf = 0; nf < 12; nf++) {
        const int col = nf * 8 + (lane & 3) * 2;
        *(__half2*)(O + baseQ + (long)rA * EMBD + col) =
            __floats2half2_rn(oa[nf][0] * s0, oa[nf][1] * s0);
        *(__half2*)(O + baseQ + (long)(rA + 8) * EMBD + col) =
            __floats2half2_rn(oa[nf][2] * s1, oa[nf][3] * s1);
    }
}

// ---------------- launch ----------------------------------------------------
extern "C" void kernel_launch(void* const* d_in, const int* in_sizes, int n_in,
                              void* d_out, int out_size) {
    const float* x     = (const float*)d_in[0];
    const float* ln1_g = (const float*)d_in[1];
    const float* ln1_b = (const float*)d_in[2];
    const float* wq    = (const float*)d_in[3];
    const float* bq    = (const float*)d_in[4];
    const float* wk    = (const float*)d_in[5];
    const float* bk    = (const float*)d_in[6];
    const float* wv    = (const float*)d_in[7];
    const float* bv    = (const float*)d_in[8];
    const float* wo    = (const float*)d_in[9];
    const float* bo    = (const float*)d_in[10];
    const float* ln2_g = (const float*)d_in[11];
    const float* ln2_b = (const float*)d_in[12];
    const float* w1    = (const float*)d_in[13];
    const float* b1    = (const float*)d_in[14];
    const float* w2    = (const float*)d_in[15];
    const float* b2    = (const float*)d_in[16];

    __half *yh, *qh, *kh, *vT, *oh, *zh, *hh;
    __half *wqT, *wkT, *wvT, *woT, *w1T, *w2T;
    float* x1;
    cudaGetSymbolAddress((void**)&yh,  g_yh);
    cudaGetSymbolAddress((void**)&qh,  g_qh);
    cudaGetSymbolAddress((void**)&kh,  g_kh);
    cudaGetSymbolAddress((void**)&vT,  g_vT);
    cudaGetSymbolAddress((void**)&oh,  g_oh);
    cudaGetSymbolAddress((void**)&zh,  g_zh);
    cudaGetSymbolAddress((void**)&hh,  g_hh);
    cudaGetSymbolAddress((void**)&x1,  g_x1);
    cudaGetSymbolAddress((void**)&wqT, g_wqT);
    cudaGetSymbolAddress((void**)&wkT, g_wkT);
    cudaGetSymbolAddress((void**)&wvT, g_wvT);
    cudaGetSymbolAddress((void**)&woT, g_woT);
    cudaGetSymbolAddress((void**)&w1T, g_w1T);
    cudaGetSymbolAddress((void**)&w2T, g_w2T);

    cudaFuncSetAttribute(attn_h,
                         cudaFuncAttributeMaxDynamicSharedMemorySize, ATT_SMEM);
    cudaFuncSetAttribute(gemm_h<0,1,0>,
                         cudaFuncAttributeMaxDynamicSharedMemorySize, GMH_SMEM);
    cudaFuncSetAttribute(gemm_h<0,1,1>,
                         cudaFuncAttributeMaxDynamicSharedMemorySize, GMH_SMEM);
    cudaFuncSetAttribute(gemm_h<1,0,0>,
                         cudaFuncAttributeMaxDynamicSharedMemorySize, GMH_SMEM);
    cudaFuncSetAttribute(gemm_h<2,1,0>,
                         cudaFuncAttributeMaxDynamicSharedMemorySize, GMH_SMEM);

    const dim3 tb(32, 8);
    convT_kernel<<<dim3(EMBD / 32, EMBD / 32), tb>>>(wq, wqT, EMBD, EMBD);
    convT_kernel<<<dim3(EMBD / 32, EMBD / 32), tb>>>(wk, wkT, EMBD, EMBD);
    convT_kernel<<<dim3(EMBD / 32, EMBD / 32), tb>>>(wv, wvT, EMBD, EMBD);
    convT_kernel<<<dim3(EMBD / 32, EMBD / 32), tb>>>(wo, woT, EMBD, EMBD);
    convT_kernel<<<dim3(DFF2 / 32, EMBD / 32), tb>>>(w1, w1T, EMBD, DFF2);
    convT_kernel<<<dim3(EMBD / 32, DFF2 / 32), tb>>>(w2, w2T, DFF2, EMBD);

    // LN1
    ln_kernel<<<TOK, 256>>>(x, ln1_g, ln1_b, yh);
    // QKV projections
    gemm_h<0,1,0><<<dim3(EMBD / 128, TOK / 128), 256, GMH_SMEM>>>(yh, wqT, bq, nullptr, qh, TOK, EMBD, EMBD);
    gemm_h<0,1,0><<<dim3(EMBD / 128, TOK / 128), 256, GMH_SMEM>>>(yh, wkT, bk, nullptr, kh, TOK, EMBD, EMBD);
    gemm_h<0,1,1><<<dim3(EMBD / 128, TOK / 128), 256, GMH_SMEM>>>(yh, wvT, bv, nullptr, vT, TOK, EMBD, EMBD);
    // attention
    attn_h<<<dim3(SEQ / FBM, NHEAD, NBATCH), 256, ATT_SMEM>>>(qh, kh, vT, oh);
    // output projection + residual (fp32 out)
    gemm_h<1,0,0><<<dim3(EMBD / 128, TOK / 128), 256, GMH_SMEM>>>(oh, woT, bo, x, x1, TOK, EMBD, EMBD);
    // LN2
    ln_kernel<<<TOK, 256>>>(x1, ln2_g, ln2_b, zh);
    // FFN
    gemm_h<2,1,0><<<dim3(DFF2 / 128, TOK / 128), 256, GMH_SMEM>>>(zh, w1T, b1, nullptr, hh, TOK, DFF2, EMBD);
    gemm_h<1,0,0><<<dim3(EMBD / 128, TOK / 128), 256, GMH_SMEM>>>(hh, w2T, b2, x1, d_out, TOK, EMBD, DFF2);
}

// round 6
// speedup vs baseline: 7.4008x; 1.0206x over previous
#include <cuda_runtime.h>
#include <cuda_fp16.h>
#include <math.h>
#include <stdint.h>

#define TOK   8192
#define EMBD  768
#define DFF2  3072
#define NHEAD 8
#define HD    96
#define SEQ   2048
#define NBATCH 4

// ---------------- scratch (device globals) ----------------------------------
__device__ __half g_yh[TOK * EMBD];
__device__ __half g_qh[TOK * EMBD];
__device__ __half g_kh[TOK * EMBD];
__device__ __half g_vT[TOK * EMBD];     // [b][h][d][seq]
__device__ __half g_oh[TOK * EMBD];
__device__ __half g_zh[TOK * EMBD];
__device__ __half g_hh[TOK * DFF2];
__device__ float  g_x1[TOK * EMBD];
// fp16 transposed weights [N][K]
__device__ __half g_wqT[EMBD * EMBD];
__device__ __half g_wkT[EMBD * EMBD];
__device__ __half g_wvT[EMBD * EMBD];
__device__ __half g_woT[EMBD * EMBD];
__device__ __half g_w1T[DFF2 * EMBD];
__device__ __half g_w2T[EMBD * DFF2];

// ---------------- helpers ----------------------------------------------------
__device__ __forceinline__ void cpasync16(uint32_t saddr, const void* gaddr) {
    asm volatile("cp.async.cg.shared.global [%0], [%1], 16;" :: "r"(saddr), "l"(gaddr));
}
#define CP_COMMIT() asm volatile("cp.async.commit_group;" ::: "memory")

__device__ __forceinline__ uint32_t smem_u32(const void* p) {
    uint32_t a;
    asm("{ .reg .u64 t; cvta.to.shared.u64 t, %1; cvt.u32.u64 %0, t; }"
        : "=r"(a) : "l"(p));
    return a;
}

__device__ __forceinline__ void mma_f16(float* c, const uint32_t* a, const uint32_t* b) {
    asm volatile(
        "mma.sync.aligned.m16n8k16.row.col.f32.f16.f16.f32 "
        "{%0,%1,%2,%3}, {%4,%5,%6,%7}, {%8,%9}, {%0,%1,%2,%3};"
        : "+f"(c[0]), "+f"(c[1]), "+f"(c[2]), "+f"(c[3])
        : "r"(a[0]), "r"(a[1]), "r"(a[2]), "r"(a[3]), "r"(b[0]), "r"(b[1]));
}

__device__ __forceinline__ void ldmx4(uint32_t* r, uint32_t saddr) {
    asm volatile("ldmatrix.sync.aligned.m8n8.x4.shared.b16 {%0,%1,%2,%3}, [%4];"
        : "=r"(r[0]), "=r"(r[1]), "=r"(r[2]), "=r"(r[3]) : "r"(saddr));
}

// ---------------- weight convert+transpose: Wt[n][k] = (half)W[k][n] --------
__global__ __launch_bounds__(256)
void convT_kernel(const float* __restrict__ W, __half* __restrict__ Wt,
                  int K, int N) {
    __shared__ float t[32][33];
    const int n0 = blockIdx.x * 32, k0 = blockIdx.y * 32;
    const int tx = threadIdx.x, ty = threadIdx.y;
    #pragma unroll
    for (int i = 0; i < 32; i += 8)
        t[ty + i][tx] = W[(long)(k0 + ty + i) * N + n0 + tx];
    __syncthreads();
    #pragma unroll
    for (int i = 0; i < 32; i += 8)
        Wt[(long)(n0 + ty + i) * K + k0 + tx] = __float2half(t[tx][ty + i]);
}

// ---------------- LayerNorm (fp32 in -> fp16 out) ---------------------------
__global__ __launch_bounds__(256)
void ln_kernel(const float* __restrict__ x, const float* __restrict__ g,
               const float* __restrict__ b, __half* __restrict__ y) {
    const int row = blockIdx.x;
    const float* xr = x + (long)row * EMBD;
    const int t = threadIdx.x;
    float v0 = xr[t], v1 = xr[t + 256], v2 = xr[t + 512];
    float s  = v0 + v1 + v2;
    float sq = v0 * v0 + v1 * v1 + v2 * v2;
    #pragma unroll
    for (int o = 16; o; o >>= 1) {
        s  += __shfl_xor_sync(0xffffffffu, s,  o);
        sq += __shfl_xor_sync(0xffffffffu, sq, o);
    }
    __shared__ float sbuf[16];
    const int w = t >> 5, l = t & 31;
    if (l == 0) { sbuf[w] = s; sbuf[w + 8] = sq; }
    __syncthreads();
    float ts = 0.f, tsq = 0.f;
    #pragma unroll
    for (int i = 0; i < 8; i++) { ts += sbuf[i]; tsq += sbuf[8 + i]; }
    const float mu  = ts * (1.0f / EMBD);
    const float var = tsq * (1.0f / EMBD) - mu * mu;
    const float r   = rsqrtf(var + 1e-5f);
    __half* yr = y + (long)row * EMBD;
    yr[t]       = __float2half((v0 - mu) * r * g[t]       + b[t]);
    yr[t + 256] = __float2half((v1 - mu) * r * g[t + 256] + b[t + 256]);
    yr[t + 512] = __float2half((v2 - mu) * r * g[t + 512] + b[t + 512]);
}

// ============ fp16 mma GEMM: C = A[M,K](h) @ Bt[N,K](h)^T + epi ==============
#define HGK    64
#define HSTR   72
#define OP_BYTES (128 * HSTR * 2)
#define HSTG   (2 * OP_BYTES)
#define GMH_SMEM (2 * HSTG)

__device__ __forceinline__ void ld_stage_h(uint32_t sa, uint32_t sb,
                                           const __half* __restrict__ A,
                                           const __half* __restrict__ Bt,
                                           int bm, int bn, int KA, int KB,
                                           int k0, int tid) {
    #pragma unroll
    for (int j = 0; j < 4; j++) {
        const int ch = tid + j * 256;
        const int r = ch >> 3, kc = ch & 7;
        cpasync16(sa + (r * HSTR + kc * 8) * 2,
                  A + (long)(bm + r) * KA + k0 + kc * 8);
    }
    #pragma unroll
    for (int j = 0; j < 4; j++) {
        const int ch = tid + j * 256;
        const int r = ch >> 3, kc = ch & 7;
        cpasync16(sb + (r * HSTR + kc * 8) * 2,
                  Bt + (long)(bn + r) * KB + k0 + kc * 8);
    }
}

template <int EPI, int OUTH, int TRV>
__global__ __launch_bounds__(256, 1)
void gemm_h(const __half* __restrict__ A, const __half* __restrict__ Bt,
            const float* __restrict__ bias, const float* __restrict__ res,
            void* __restrict__ Cout, int M, int N, int K) {
    extern __shared__ __half smh[];
    const uint32_t sbase = smem_u32(smh);

    const int tid  = threadIdx.x;
    const int lane = tid & 31;
    const int wid  = tid >> 5;
    const int bm = blockIdx.y * 128;
    const int bn = blockIdx.x * 128;
    const int wm = (wid & 1) * 64;
    const int wn = (wid >> 1) * 32;

    // ldmatrix per-lane source rows/cols
    const int aRow = wm + (lane & 15);          // A: row within 16-row frag
    const int aK   = (lane >> 4) * 8;           // A: k-half select
    const int bRow = wn + ((lane >> 4) & 1) * 8 + (lane & 7);  // B: n row
    const int bK   = ((lane >> 3) & 1) * 8;     // B: k-half select

    float acc[4][4][4];
    #pragma unroll
    for (int mi = 0; mi < 4; mi++)
        #pragma unroll
        for (int ni = 0; ni < 4; ni++)
            #pragma unroll
            for (int u = 0; u < 4; u++) acc[mi][ni][u] = 0.f;

    const int nkt = K / HGK;
    ld_stage_h(sbase, sbase + OP_BYTES, A, Bt, bm, bn, K, K, 0, tid);
    CP_COMMIT();

    for (int kt = 0; kt < nkt; kt++) {
        const uint32_t fA_u = sbase + (kt & 1) * HSTG;
        const uint32_t fB_u = fA_u + OP_BYTES;

        if (kt + 1 < nkt) {
            const uint32_t sn = sbase + ((kt + 1) & 1) * HSTG;
            ld_stage_h(sn, sn + OP_BYTES, A, Bt, bm, bn, K, K, (kt + 1) * HGK, tid);
            CP_COMMIT();
            asm volatile("cp.async.wait_group 1;" ::: "memory");
        } else {
            asm volatile("cp.async.wait_group 0;" ::: "memory");
        }
        __syncthreads();

        #pragma unroll
        for (int ks = 0; ks < 4; ks++) {
            uint32_t af[4][4];
            #pragma unroll
            for (int mi = 0; mi < 4; mi++)
                ldmx4(af[mi], fA_u + ((aRow + mi * 16) * HSTR + ks * 16 + aK) * 2);
            uint32_t bb[2][4];
            #pragma unroll
            for (int nj = 0; nj < 2; nj++)
                ldmx4(bb[nj], fB_u + ((bRow + nj * 16) * HSTR + ks * 16 + bK) * 2);
            #pragma unroll
            for (int mi = 0; mi < 4; mi++)
                #pragma unroll
                for (int nj = 0; nj < 2; nj++) {
                    mma_f16(acc[mi][nj * 2 + 0], af[mi], &bb[nj][0]);
                    mma_f16(acc[mi][nj * 2 + 1], af[mi], &bb[nj][2]);
                }
        }
        __syncthreads();
    }

    const int erow = bm + wm + (lane >> 2);
    const int ecol = bn + wn + (lane & 3) * 2;
    #pragma unroll
    for (int mi = 0; mi < 4; mi++) {
        #pragma unroll
        for (int half = 0; half < 2; half++) {
            const long r = erow + mi * 16 + half * 8;
            #pragma unroll
            for (int ni = 0; ni < 4; ni++) {
                const int c = ecol + ni * 8;
                float v0 = acc[mi][ni][half * 2 + 0] + bias[c];
                float v1 = acc[mi][ni][half * 2 + 1] + bias[c + 1];
                if (EPI == 2) {
                    v0 = 0.5f * v0 * (1.0f + erff(v0 * 0.70710678118654752f));
                    v1 = 0.5f * v1 * (1.0f + erff(v1 * 0.70710678118654752f));
                }
                if (EPI == 1) {
                    v0 += res[r * N + c];
                    v1 += res[r * N + c + 1];
                }
                if (TRV) {
                    const int bb2 = (int)(r >> 11), sidx = (int)(r & 2047);
                    __half* vt = (__half*)Cout;
                    const long o0 = ((long)(bb2 * NHEAD + c / HD) * HD + (c % HD)) * SEQ + sidx;
                    const long o1 = ((long)(bb2 * NHEAD + (c + 1) / HD) * HD + ((c + 1) % HD)) * SEQ + sidx;
                    vt[o0] = __float2half(v0);
                    vt[o1] = __float2half(v1);
                } else if (OUTH) {
                    *(__half2*)((__half*)Cout + r * N + c) = __floats2half2_rn(v0, v1);
                } else {
                    *(float2*)((float*)Cout + r * N + c) = make_float2(v0, v1);
                }
            }
        }
    }
}

// =================== fp16 flash attention ===================================
#define FBM    128
#define FBN    64
#define QSTR_H 104
#define KSTR_H 104
#define VSTR_H 72
#define PSTR_H 72
#define SQ_H   (FBM * QSTR_H)
#define SP_H   (FBM * PSTR_H)
#define KV_H   (FBN * KSTR_H + HD * VSTR_H)
#define ATT_SMEM ((SQ_H + SP_H + 2 * KV_H) * 2)

__device__ __forceinline__ void attn_ld_kv_h(uint32_t sk, uint32_t sv,
                                             const __half* __restrict__ K,
                                             const __half* __restrict__ VT,
                                             long baseKV, long baseVT,
                                             int kt, int tid) {
    #pragma unroll
    for (int j = 0; j < 3; j++) {
        const int ch = tid + j * 256;
        const int r = ch / 12, c = ch % 12;
        cpasync16(sk + (r * KSTR_H + c * 8) * 2,
                  K + baseKV + (long)(kt * FBN + r) * EMBD + c * 8);
    }
    #pragma unroll
    for (int j = 0; j < 3; j++) {
        const int ch = tid + j * 256;
        const int d = ch >> 3, sc = ch & 7;
        cpasync16(sv + (d * VSTR_H + sc * 8) * 2,
                  VT + baseVT + (long)d * SEQ + kt * FBN + sc * 8);
    }
}

__global__ __launch_bounds__(256, 1)
void attn_h(const __half* __restrict__ Q, const __half* __restrict__ K,
            const __half* __restrict__ VT, __half* __restrict__ O) {
    extern __shared__ __half smh[];
    __half* sQ = smh;
    __half* sP = sQ + SQ_H;
    __half* sKV = sP + SP_H;
    const uint32_t sQ_u  = smem_u32(sQ);
    const uint32_t sP_u  = smem_u32(sP);
    const uint32_t skv_u = smem_u32(sKV);

    const int b  = blockIdx.z;
    const int h  = blockIdx.y;
    const int qt = blockIdx.x;
    const int tid  = threadIdx.x;
    const int lane = tid & 31;
    const int wid  = tid >> 5;

    const long baseQ  = ((long)(b * SEQ + qt * FBM)) * EMBD + h * HD;
    const long baseKV = ((long)(b * SEQ)) * EMBD + h * HD;
    const long baseVT = (long)(b * NHEAD + h) * HD * SEQ;

    for (int i = tid; i < FBM * 12; i += 256) {
        const int r = i / 12, c = i % 12;
        cpasync16(sQ_u + (r * QSTR_H + c * 8) * 2,
                  Q + baseQ + (long)r * EMBD + c * 8);
    }
    attn_ld_kv_h(skv_u, skv_u + FBN * KSTR_H * 2, K, VT, baseKV, baseVT, 0, tid);
    CP_COMMIT();

    // ldmatrix lane mapping
    const int aRow = wid * 16 + (lane & 15);
    const int aK   = (lane >> 4) * 8;
    const int bRow = ((lane >> 4) & 1) * 8 + (lane & 7);
    const int bK   = ((lane >> 3) & 1) * 8;
    const int rA = wid * 16 + (lane >> 2);

    float m0 = -1e30f, m1 = -1e30f, l0 = 0.f, l1 = 0.f;
    float oa[12][4];
    #pragma unroll
    for (int nf = 0; nf < 12; nf++)
        #pragma unroll
        for (int u = 0; u < 4; u++) oa[nf][u] = 0.f;

    const int NIT = SEQ / FBN;
    for (int it = 0; it < NIT; it++) {
        const uint32_t fK_u = skv_u + (it & 1) * KV_H * 2;
        const uint32_t fV_u = fK_u + FBN * KSTR_H * 2;

        __syncthreads();
        if (it + 1 < NIT) {
            const uint32_t sn = skv_u + ((it + 1) & 1) * KV_H * 2;
            attn_ld_kv_h(sn, sn + FBN * KSTR_H * 2, K, VT, baseKV, baseVT, it + 1, tid);
            CP_COMMIT();
            asm volatile("cp.async.wait_group 1;" ::: "memory");
        } else {
            asm volatile("cp.async.wait_group 0;" ::: "memory");
        }
        __syncthreads();

        // ---- S = Q K^T ----
        float sc[8][4];
        #pragma unroll
        for (int nf = 0; nf < 8; nf++)
            #pragma unroll
            for (int u = 0; u < 4; u++) sc[nf][u] = 0.f;

        #pragma unroll
        for (int ks = 0; ks < 6; ks++) {
            uint32_t af[4];
            ldmx4(af, sQ_u + (aRow * QSTR_H + ks * 16 + aK) * 2);
            #pragma unroll
            for (int nj = 0; nj < 4; nj++) {
                uint32_t bb[4];
                ldmx4(bb, fK_u + ((bRow + nj * 16) * KSTR_H + ks * 16 + bK) * 2);
                mma_f16(sc[nj * 2 + 0], af, &bb[0]);
                mma_f16(sc[nj * 2 + 1], af, &bb[2]);
            }
        }

        // ---- online softmax ----
        float t0 = -1e30f, t1 = -1e30f;
        #pragma unroll
        for (int nf = 0; nf < 8; nf++) {
            t0 = fmaxf(t0, fmaxf(sc[nf][0], sc[nf][1]));
            t1 = fmaxf(t1, fmaxf(sc[nf][2], sc[nf][3]));
        }
        t0 = fmaxf(t0, __shfl_xor_sync(0xffffffffu, t0, 1));
        t0 = fmaxf(t0, __shfl_xor_sync(0xffffffffu, t0, 2));
        t1 = fmaxf(t1, __shfl_xor_sync(0xffffffffu, t1, 1));
        t1 = fmaxf(t1, __shfl_xor_sync(0xffffffffu, t1, 2));
        const float mn0 = fmaxf(m0, t0), mn1 = fmaxf(m1, t1);
        const float cr0 = __expf(m0 - mn0), cr1 = __expf(m1 - mn1);
        float rs0 = 0.f, rs1 = 0.f;
        #pragma unroll
        for (int nf = 0; nf < 8; nf++) {
            const float p00 = __expf(sc[nf][0] - mn0);
            const float p01 = __expf(sc[nf][1] - mn0);
            const float p10 = __expf(sc[nf][2] - mn1);
            const float p11 = __expf(sc[nf][3] - mn1);
            rs0 += p00 + p01; rs1 += p10 + p11;
            const int col = nf * 8 + (lane & 3) * 2;
            *(__half2*)&sP[rA * PSTR_H + col]       = __floats2half2_rn(p00, p01);
            *(__half2*)&sP[(rA + 8) * PSTR_H + col] = __floats2half2_rn(p10, p11);
        }
        rs0 += __shfl_xor_sync(0xffffffffu, rs0, 1);
        rs0 += __shfl_xor_sync(0xffffffffu, rs0, 2);
        rs1 += __shfl_xor_sync(0xffffffffu, rs1, 1);
        rs1 += __shfl_xor_sync(0xffffffffu, rs1, 2);
        l0 = l0 * cr0 + rs0; m0 = mn0;
        l1 = l1 * cr1 + rs1; m1 = mn1;
        #pragma unroll
        for (int nf = 0; nf < 12; nf++) {
            oa[nf][0] *= cr0; oa[nf][1] *= cr0;
            oa[nf][2] *= cr1; oa[nf][3] *= cr1;
        }
        __syncwarp();

        // ---- O += P V ----
        #pragma unroll
        for (int ks = 0; ks < 4; ks++) {
            uint32_t af[4];
            ldmx4(af, sP_u + (aRow * PSTR_H + ks * 16 + aK) * 2);
            #pragma unroll
            for (int nj = 0; nj < 6; nj++) {
                uint32_t bb[4];
                ldmx4(bb, fV_u + ((bRow + nj * 16) * VSTR_H + ks * 16 + bK) * 2);
                mma_f16(oa[nj * 2 + 0], af, &bb[0]);
                mma_f16(oa[nj * 2 + 1], af, &bb[2]);
            }
        }
        __syncwarp();
    }

    const float s0 = 1.0f / (l0 * 27.712812921102035f);
    const float s1 = 1.0f / (l1 * 27.712812921102035f);
    #pragma unroll
    for (int nf = 0; nf < 12; nf++) {
        const int col = nf * 8 + (lane & 3) * 2;
        *(__half2*)(O + baseQ + (long)rA * EMBD + col) =
            __floats2half2_rn(oa[nf][0] * s0, oa[nf][1] * s0);
        *(__half2*)(O + baseQ + (long)(rA + 8) * EMBD + col) =
            __floats2half2_rn(oa[nf][2] * s1, oa[nf][3] * s1);
    }
}

// ---------------- launch ----------------------------------------------------
extern "C" void kernel_launch(void* const* d_in, const int* in_sizes, int n_in,
                              void* d_out, int out_size) {
    const float* x     = (const float*)d_in[0];
    const float* ln1_g = (const float*)d_in[1];
    const float* ln1_b = (const float*)d_in[2];
    const float* wq    = (const float*)d_in[3];
    const float* bq    = (const float*)d_in[4];
    const float* wk    = (const float*)d_in[5];
    const float* bk    = (const float*)d_in[6];
    const float* wv    = (const float*)d_in[7];
    const float* bv    = (const float*)d_in[8];
    const float* wo    = (const float*)d_in[9];
    const float* bo    = (const float*)d_in[10];
    const float* ln2_g = (const float*)d_in[11];
    const float* ln2_b = (const float*)d_in[12];
    const float* w1    = (const float*)d_in[13];
    const float* b1    = (const float*)d_in[14];
    const float* w2    = (const float*)d_in[15];
    const float* b2    = (const float*)d_in[16];

    __half *yh, *qh, *kh, *vT, *oh, *zh, *hh;
    __half *wqT, *wkT, *wvT, *woT, *w1T, *w2T;
    float* x1;
    cudaGetSymbolAddress((void**)&yh,  g_yh);
    cudaGetSymbolAddress((void**)&qh,  g_qh);
    cudaGetSymbolAddress((void**)&kh,  g_kh);
    cudaGetSymbolAddress((void**)&vT,  g_vT);
    cudaGetSymbolAddress((void**)&oh,  g_oh);
    cudaGetSymbolAddress((void**)&zh,  g_zh);
    cudaGetSymbolAddress((void**)&hh,  g_hh);
    cudaGetSymbolAddress((void**)&x1,  g_x1);
    cudaGetSymbolAddress((void**)&wqT, g_wqT);
    cudaGetSymbolAddress((void**)&wkT, g_wkT);
    cudaGetSymbolAddress((void**)&wvT, g_wvT);
    cudaGetSymbolAddress((void**)&woT, g_woT);
    cudaGetSymbolAddress((void**)&w1T, g_w1T);
    cudaGetSymbolAddress((void**)&w2T, g_w2T);

    cudaFuncSetAttribute(attn_h,
                         cudaFuncAttributeMaxDynamicSharedMemorySize, ATT_SMEM);
    cudaFuncSetAttribute(gemm_h<0,1,0>,
                         cudaFuncAttributeMaxDynamicSharedMemorySize, GMH_SMEM);
    cudaFuncSetAttribute(gemm_h<0,1,1>,
                         cudaFuncAttributeMaxDynamicSharedMemorySize, GMH_SMEM);
    cudaFuncSetAttribute(gemm_h<1,0,0>,
                         cudaFuncAttributeMaxDynamicSharedMemorySize, GMH_SMEM);
    cudaFuncSetAttribute(gemm_h<2,1,0>,
                         cudaFuncAttributeMaxDynamicSharedMemorySize, GMH_SMEM);

    const dim3 tb(32, 8);
    convT_kernel<<<dim3(EMBD / 32, EMBD / 32), tb>>>(wq, wqT, EMBD, EMBD);
    convT_kernel<<<dim3(EMBD / 32, EMBD / 32), tb>>>(wk, wkT, EMBD, EMBD);
    convT_kernel<<<dim3(EMBD / 32, EMBD / 32), tb>>>(wv, wvT, EMBD, EMBD);
    convT_kernel<<<dim3(EMBD / 32, EMBD / 32), tb>>>(wo, woT, EMBD, EMBD);
    convT_kernel<<<dim3(DFF2 / 32, EMBD / 32), tb>>>(w1, w1T, EMBD, DFF2);
    convT_kernel<<<dim3(EMBD / 32, DFF2 / 32), tb>>>(w2, w2T, DFF2, EMBD);

    // LN1
    ln_kernel<<<TOK, 256>>>(x, ln1_g, ln1_b, yh);
    // QKV projections
    gemm_h<0,1,0><<<dim3(EMBD / 128, TOK / 128), 256, GMH_SMEM>>>(yh, wqT, bq, nullptr, qh, TOK, EMBD, EMBD);
    gemm_h<0,1,0><<<dim3(EMBD / 128, TOK / 128), 256, GMH_SMEM>>>(yh, wkT, bk, nullptr, kh, TOK, EMBD, EMBD);
    gemm_h<0,1,1><<<dim3(EMBD / 128, TOK / 128), 256, GMH_SMEM>>>(yh, wvT, bv, nullptr, vT, TOK, EMBD, EMBD);
    // attention
    attn_h<<<dim3(SEQ / FBM, NHEAD, NBATCH), 256, ATT_SMEM>>>(qh, kh, vT, oh);
    // output projection + residual (fp32 out)
    gemm_h<1,0,0><<<dim3(EMBD / 128, TOK / 128), 256, GMH_SMEM>>>(oh, woT, bo, x, x1, TOK, EMBD, EMBD);
    // LN2
    ln_kernel<<<TOK, 256>>>(x1, ln2_g, ln2_b, zh);
    // FFN
    gemm_h<2,1,0><<<dim3(DFF2 / 128, TOK / 128), 256, GMH_SMEM>>>(zh, w1T, b1, nullptr, hh, TOK, DFF2, EMBD);
    gemm_h<1,0,0><<<dim3(EMBD / 128, TOK / 128), 256, GMH_SMEM>>>(hh, w2T, b2, x1, d_out, TOK, EMBD, DFF2);
}

// round 7
// speedup vs baseline: 7.6333x; 1.0314x over previous
#include <cuda_runtime.h>
#include <cuda_fp16.h>
#include <math.h>
#include <stdint.h>

#define TOK   8192
#define EMBD  768
#define DFF2  3072
#define NHEAD 8
#define HD    96
#define SEQ   2048
#define NBATCH 4
#define NQKV  2304

// ---------------- scratch (device globals) ----------------------------------
__device__ __half g_yh[TOK * EMBD];
__device__ __half g_qh[TOK * EMBD];
__device__ __half g_kh[TOK * EMBD];
__device__ __half g_vT[TOK * EMBD];     // [b][h][d][seq]
__device__ __half g_oh[TOK * EMBD];
__device__ __half g_zh[TOK * EMBD];
__device__ __half g_hh[TOK * DFF2];
__device__ float  g_x1[TOK * EMBD];
__device__ __half g_wqkvT[NQKV * EMBD]; // [2304][768]: wq|wk|wv transposed
__device__ float  g_bqkv[NQKV];
__device__ __half g_woT[EMBD * EMBD];
__device__ __half g_w1T[DFF2 * EMBD];
__device__ __half g_w2T[EMBD * DFF2];

// ---------------- helpers ----------------------------------------------------
__device__ __forceinline__ void cpasync16(uint32_t saddr, const void* gaddr) {
    asm volatile("cp.async.cg.shared.global [%0], [%1], 16;" :: "r"(saddr), "l"(gaddr));
}
#define CP_COMMIT() asm volatile("cp.async.commit_group;" ::: "memory")

__device__ __forceinline__ uint32_t smem_u32(const void* p) {
    uint32_t a;
    asm("{ .reg .u64 t; cvta.to.shared.u64 t, %1; cvt.u32.u64 %0, t; }"
        : "=r"(a) : "l"(p));
    return a;
}

__device__ __forceinline__ void mma_f16(float* c, const uint32_t* a, const uint32_t* b) {
    asm volatile(
        "mma.sync.aligned.m16n8k16.row.col.f32.f16.f16.f32 "
        "{%0,%1,%2,%3}, {%4,%5,%6,%7}, {%8,%9}, {%0,%1,%2,%3};"
        : "+f"(c[0]), "+f"(c[1]), "+f"(c[2]), "+f"(c[3])
        : "r"(a[0]), "r"(a[1]), "r"(a[2]), "r"(a[3]), "r"(b[0]), "r"(b[1]));
}

__device__ __forceinline__ void ldmx4(uint32_t* r, uint32_t saddr) {
    asm volatile("ldmatrix.sync.aligned.m8n8.x4.shared.b16 {%0,%1,%2,%3}, [%4];"
        : "=r"(r[0]), "=r"(r[1]), "=r"(r[2]), "=r"(r[3]) : "r"(saddr));
}

// ---------------- weight convert+transpose: Wt[n][k] = (half)W[k][n] --------
__global__ __launch_bounds__(256)
void convT_kernel(const float* __restrict__ W, __half* __restrict__ Wt,
                  int K, int N) {
    __shared__ float t[32][33];
    const int n0 = blockIdx.x * 32, k0 = blockIdx.y * 32;
    const int tx = threadIdx.x, ty = threadIdx.y;
    #pragma unroll
    for (int i = 0; i < 32; i += 8)
        t[ty + i][tx] = W[(long)(k0 + ty + i) * N + n0 + tx];
    __syncthreads();
    #pragma unroll
    for (int i = 0; i < 32; i += 8)
        Wt[(long)(n0 + ty + i) * K + k0 + tx] = __float2half(t[tx][ty + i]);
}

__global__ void bias_cat_kernel(const float* bq, const float* bk, const float* bv,
                                float* out) {
    const int i = blockIdx.x * 256 + threadIdx.x;
    if (i < EMBD) { out[i] = bq[i]; out[i + EMBD] = bk[i]; out[i + 2 * EMBD] = bv[i]; }
}

// ---------------- LayerNorm (fp32 in -> fp16 out) ---------------------------
__global__ __launch_bounds__(256)
void ln_kernel(const float* __restrict__ x, const float* __restrict__ g,
               const float* __restrict__ b, __half* __restrict__ y) {
    const int row = blockIdx.x;
    const float* xr = x + (long)row * EMBD;
    const int t = threadIdx.x;
    float v0 = xr[t], v1 = xr[t + 256], v2 = xr[t + 512];
    float s  = v0 + v1 + v2;
    float sq = v0 * v0 + v1 * v1 + v2 * v2;
    #pragma unroll
    for (int o = 16; o; o >>= 1) {
        s  += __shfl_xor_sync(0xffffffffu, s,  o);
        sq += __shfl_xor_sync(0xffffffffu, sq, o);
    }
    __shared__ float sbuf[16];
    const int w = t >> 5, l = t & 31;
    if (l == 0) { sbuf[w] = s; sbuf[w + 8] = sq; }
    __syncthreads();
    float ts = 0.f, tsq = 0.f;
    #pragma unroll
    for (int i = 0; i < 8; i++) { ts += sbuf[i]; tsq += sbuf[8 + i]; }
    const float mu  = ts * (1.0f / EMBD);
    const float var = tsq * (1.0f / EMBD) - mu * mu;
    const float r   = rsqrtf(var + 1e-5f);
    __half* yr = y + (long)row * EMBD;
    yr[t]       = __float2half((v0 - mu) * r * g[t]       + b[t]);
    yr[t + 256] = __float2half((v1 - mu) * r * g[t + 256] + b[t + 256]);
    yr[t + 512] = __float2half((v2 - mu) * r * g[t + 512] + b[t + 512]);
}

// ============ fp16 mma GEMM: tile 128x64, 8 warps (32x32 warptile) ==========
// EPI: 0 bias(->h), 1 bias+res(->f32), 2 bias+GELU(->h), 3 QKV split epilogue
#define HGK    64
#define HSTR   72
#define A_HB   (128 * HSTR * 2)
#define B_HB   (64 * HSTR * 2)
#define STG_HB (A_HB + B_HB)
#define NSTG   3
#define GMH_SMEM (NSTG * STG_HB)

__device__ __forceinline__ void ld_stage_h(uint32_t sa,
                                           const __half* __restrict__ A,
                                           const __half* __restrict__ Bt,
                                           int bm, int bn, int K,
                                           int k0, int tid) {
    #pragma unroll
    for (int j = 0; j < 4; j++) {
        const int ch = tid + j * 256;
        const int r = ch >> 3, kc = ch & 7;
        cpasync16(sa + (r * HSTR + kc * 8) * 2,
                  A + (long)(bm + r) * K + k0 + kc * 8);
    }
    const uint32_t sb = sa + A_HB;
    #pragma unroll
    for (int j = 0; j < 2; j++) {
        const int ch = tid + j * 256;
        const int r = ch >> 3, kc = ch & 7;
        cpasync16(sb + (r * HSTR + kc * 8) * 2,
                  Bt + (long)(bn + r) * K + k0 + kc * 8);
    }
}

template <int EPI>
__global__ __launch_bounds__(256, 2)
void gemm_h(const __half* __restrict__ A, const __half* __restrict__ Bt,
            const float* __restrict__ bias, const float* __restrict__ res,
            void* __restrict__ Cout, int M, int N, int K) {
    extern __shared__ __half smh[];
    const uint32_t sbase = smem_u32(smh);

    const int tid  = threadIdx.x;
    const int lane = tid & 31;
    const int wid  = tid >> 5;
    const int bm = blockIdx.y * 128;
    const int bn = blockIdx.x * 64;
    const int wm = (wid & 3) * 32;
    const int wn = (wid >> 2) * 32;

    const int aRow = wm + (lane & 15);
    const int aK   = (lane >> 4) * 8;
    const int bRow = wn + ((lane >> 4) & 1) * 8 + (lane & 7);
    const int bK   = ((lane >> 3) & 1) * 8;

    float acc[2][4][4];
    #pragma unroll
    for (int mi = 0; mi < 2; mi++)
        #pragma unroll
        for (int ni = 0; ni < 4; ni++)
            #pragma unroll
            for (int u = 0; u < 4; u++) acc[mi][ni][u] = 0.f;

    const int nkt = K / HGK;
    #pragma unroll
    for (int p = 0; p < NSTG; p++) {
        if (p < nkt) ld_stage_h(sbase + p * STG_HB, A, Bt, bm, bn, K, p * HGK, tid);
        CP_COMMIT();
    }

    int sidx = 0;
    for (int kt = 0; kt < nkt; kt++) {
        const uint32_t fA_u = sbase + sidx * STG_HB;
        const uint32_t fB_u = fA_u + A_HB;

        asm volatile("cp.async.wait_group %0;" :: "n"(NSTG - 1) : "memory");
        __syncthreads();

        #pragma unroll
        for (int ks = 0; ks < 4; ks++) {
            uint32_t af[2][4];
            #pragma unroll
            for (int mi = 0; mi < 2; mi++)
                ldmx4(af[mi], fA_u + ((aRow + mi * 16) * HSTR + ks * 16 + aK) * 2);
            uint32_t bb[2][4];
            #pragma unroll
            for (int nj = 0; nj < 2; nj++)
                ldmx4(bb[nj], fB_u + ((bRow + nj * 16) * HSTR + ks * 16 + bK) * 2);
            #pragma unroll
            for (int mi = 0; mi < 2; mi++)
                #pragma unroll
                for (int nj = 0; nj < 2; nj++) {
                    mma_f16(acc[mi][nj * 2 + 0], af[mi], &bb[nj][0]);
                    mma_f16(acc[mi][nj * 2 + 1], af[mi], &bb[nj][2]);
                }
        }
        __syncthreads();

        const int next = kt + NSTG;
        if (next < nkt)
            ld_stage_h(sbase + sidx * STG_HB, A, Bt, bm, bn, K, next * HGK, tid);
        CP_COMMIT();
        sidx = (sidx + 1 == NSTG) ? 0 : sidx + 1;
    }

    const int erow = bm + wm + (lane >> 2);
    const int ecol = bn + wn + (lane & 3) * 2;
    #pragma unroll
    for (int mi = 0; mi < 2; mi++) {
        #pragma unroll
        for (int half = 0; half < 2; half++) {
            const long r = erow + mi * 16 + half * 8;
            #pragma unroll
            for (int ni = 0; ni < 4; ni++) {
                const int c = ecol + ni * 8;
                float v0 = acc[mi][ni][half * 2 + 0] + bias[c];
                float v1 = acc[mi][ni][half * 2 + 1] + bias[c + 1];
                if (EPI == 2) {
                    v0 = 0.5f * v0 * (1.0f + erff(v0 * 0.70710678118654752f));
                    v1 = 0.5f * v1 * (1.0f + erff(v1 * 0.70710678118654752f));
                }
                if (EPI == 1) {
                    v0 += res[r * N + c];
                    v1 += res[r * N + c + 1];
                }
                if (EPI == 3) {
                    if (c < EMBD) {
                        *(__half2*)&g_qh[r * EMBD + c] = __floats2half2_rn(v0, v1);
                    } else if (c < 2 * EMBD) {
                        *(__half2*)&g_kh[r * EMBD + c - EMBD] = __floats2half2_rn(v0, v1);
                    } else {
                        const int cc = c - 2 * EMBD;
                        const int bb2 = (int)(r >> 11), srow = (int)(r & 2047);
                        g_vT[((long)(bb2 * NHEAD + cc / HD) * HD + (cc % HD)) * SEQ + srow] = __float2half(v0);
                        g_vT[((long)(bb2 * NHEAD + (cc + 1) / HD) * HD + ((cc + 1) % HD)) * SEQ + srow] = __float2half(v1);
                    }
                } else if (EPI == 1) {
                    *(float2*)((float*)Cout + r * N + c) = make_float2(v0, v1);
                } else {
                    *(__half2*)((__half*)Cout + r * N + c) = __floats2half2_rn(v0, v1);
                }
            }
        }
    }
}

// =================== fp16 flash attention (unchanged) ========================
#define FBM    128
#define FBN    64
#define QSTR_H 104
#define KSTR_H 104
#define VSTR_H 72
#define PSTR_H 72
#define SQ_H   (FBM * QSTR_H)
#define SP_H   (FBM * PSTR_H)
#define KV_H   (FBN * KSTR_H + HD * VSTR_H)
#define ATT_SMEM ((SQ_H + SP_H + 2 * KV_H) * 2)

__device__ __forceinline__ void attn_ld_kv_h(uint32_t sk, uint32_t sv,
                                             const __half* __restrict__ K,
                                             const __half* __restrict__ VT,
                                             long baseKV, long baseVT,
                                             int kt, int tid) {
    #pragma unroll
    for (int j = 0; j < 3; j++) {
        const int ch = tid + j * 256;
        const int r = ch / 12, c = ch % 12;
        cpasync16(sk + (r * KSTR_H + c * 8) * 2,
                  K + baseKV + (long)(kt * FBN + r) * EMBD + c * 8);
    }
    #pragma unroll
    for (int j = 0; j < 3; j++) {
        const int ch = tid + j * 256;
        const int d = ch >> 3, sc = ch & 7;
        cpasync16(sv + (d * VSTR_H + sc * 8) * 2,
                  VT + baseVT + (long)d * SEQ + kt * FBN + sc * 8);
    }
}

__global__ __launch_bounds__(256, 1)
void attn_h(const __half* __restrict__ Q, const __half* __restrict__ K,
            const __half* __restrict__ VT, __half* __restrict__ O) {
    extern __shared__ __half smh[];
    __half* sQ = smh;
    __half* sP = sQ + SQ_H;
    __half* sKV = sP + SP_H;
    const uint32_t sQ_u  = smem_u32(sQ);
    const uint32_t sP_u  = smem_u32(sP);
    const uint32_t skv_u = smem_u32(sKV);

    const int b  = blockIdx.z;
    const int h  = blockIdx.y;
    const int qt = blockIdx.x;
    const int tid  = threadIdx.x;
    const int lane = tid & 31;
    const int wid  = tid >> 5;

    const long baseQ  = ((long)(b * SEQ + qt * FBM)) * EMBD + h * HD;
    const long baseKV = ((long)(b * SEQ)) * EMBD + h * HD;
    const long baseVT = (long)(b * NHEAD + h) * HD * SEQ;

    for (int i = tid; i < FBM * 12; i += 256) {
        const int r = i / 12, c = i % 12;
        cpasync16(sQ_u + (r * QSTR_H + c * 8) * 2,
                  Q + baseQ + (long)r * EMBD + c * 8);
    }
    attn_ld_kv_h(skv_u, skv_u + FBN * KSTR_H * 2, K, VT, baseKV, baseVT, 0, tid);
    CP_COMMIT();

    const int aRow = wid * 16 + (lane & 15);
    const int aK   = (lane >> 4) * 8;
    const int bRow = ((lane >> 4) & 1) * 8 + (lane & 7);
    const int bK   = ((lane >> 3) & 1) * 8;
    const int rA = wid * 16 + (lane >> 2);

    float m0 = -1e30f, m1 = -1e30f, l0 = 0.f, l1 = 0.f;
    float oa[12][4];
    #pragma unroll
    for (int nf = 0; nf < 12; nf++)
        #pragma unroll
        for (int u = 0; u < 4; u++) oa[nf][u] = 0.f;

    const int NIT = SEQ / FBN;
    for (int it = 0; it < NIT; it++) {
        const uint32_t fK_u = skv_u + (it & 1) * KV_H * 2;
        const uint32_t fV_u = fK_u + FBN * KSTR_H * 2;

        __syncthreads();
        if (it + 1 < NIT) {
            const uint32_t sn = skv_u + ((it + 1) & 1) * KV_H * 2;
            attn_ld_kv_h(sn, sn + FBN * KSTR_H * 2, K, VT, baseKV, baseVT, it + 1, tid);
            CP_COMMIT();
            asm volatile("cp.async.wait_group 1;" ::: "memory");
        } else {
            asm volatile("cp.async.wait_group 0;" ::: "memory");
        }
        __syncthreads();

        float sc[8][4];
        #pragma unroll
        for (int nf = 0; nf < 8; nf++)
            #pragma unroll
            for (int u = 0; u < 4; u++) sc[nf][u] = 0.f;

        #pragma unroll
        for (int ks = 0; ks < 6; ks++) {
            uint32_t af[4];
            ldmx4(af, sQ_u + (aRow * QSTR_H + ks * 16 + aK) * 2);
            #pragma unroll
            for (int nj = 0; nj < 4; nj++) {
                uint32_t bb[4];
                ldmx4(bb, fK_u + ((bRow + nj * 16) * KSTR_H + ks * 16 + bK) * 2);
                mma_f16(sc[nj * 2 + 0], af, &bb[0]);
                mma_f16(sc[nj * 2 + 1], af, &bb[2]);
            }
        }

        float t0 = -1e30f, t1 = -1e30f;
        #pragma unroll
        for (int nf = 0; nf < 8; nf++) {
            t0 = fmaxf(t0, fmaxf(sc[nf][0], sc[nf][1]));
            t1 = fmaxf(t1, fmaxf(sc[nf][2], sc[nf][3]));
        }
        t0 = fmaxf(t0, __shfl_xor_sync(0xffffffffu, t0, 1));
        t0 = fmaxf(t0, __shfl_xor_sync(0xffffffffu, t0, 2));
        t1 = fmaxf(t1, __shfl_xor_sync(0xffffffffu, t1, 1));
        t1 = fmaxf(t1, __shfl_xor_sync(0xffffffffu, t1, 2));
        const float mn0 = fmaxf(m0, t0), mn1 = fmaxf(m1, t1);
        const float cr0 = __expf(m0 - mn0), cr1 = __expf(m1 - mn1);
        float rs0 = 0.f, rs1 = 0.f;
        #pragma unroll
        for (int nf = 0; nf < 8; nf++) {
            const float p00 = __expf(sc[nf][0] - mn0);
            const float p01 = __expf(sc[nf][1] - mn0);
            const float p10 = __expf(sc[nf][2] - mn1);
            const float p11 = __expf(sc[nf][3] - mn1);
            rs0 += p00 + p01; rs1 += p10 + p11;
            const int col = nf * 8 + (lane & 3) * 2;
            *(__half2*)&sP[rA * PSTR_H + col]       = __floats2half2_rn(p00, p01);
            *(__half2*)&sP[(rA + 8) * PSTR_H + col] = __floats2half2_rn(p10, p11);
        }
        rs0 += __shfl_xor_sync(0xffffffffu, rs0, 1);
        rs0 += __shfl_xor_sync(0xffffffffu, rs0, 2);
        rs1 += __shfl_xor_sync(0xffffffffu, rs1, 1);
        rs1 += __shfl_xor_sync(0xffffffffu, rs1, 2);
        l0 = l0 * cr0 + rs0; m0 = mn0;
        l1 = l1 * cr1 + rs1; m1 = mn1;
        #pragma unroll
        for (int nf = 0; nf < 12; nf++) {
            oa[nf][0] *= cr0; oa[nf][1] *= cr0;
            oa[nf][2] *= cr1; oa[nf][3] *= cr1;
        }
        __syncwarp();

        #pragma unroll
        for (int ks = 0; ks < 4; ks++) {
            uint32_t af[4];
            ldmx4(af, sP_u + (aRow * PSTR_H + ks * 16 + aK) * 2);
            #pragma unroll
            for (int nj = 0; nj < 6; nj++) {
                uint32_t bb[4];
                ldmx4(bb, fV_u + ((bRow + nj * 16) * VSTR_H + ks * 16 + bK) * 2);
                mma_f16(oa[nj * 2 + 0], af, &bb[0]);
                mma_f16(oa[nj * 2 + 1], af, &bb[2]);
            }
        }
        __syncwarp();
    }

    const float s0 = 1.0f / (l0 * 27.712812921102035f);
    const float s1 = 1.0f / (l1 * 27.712812921102035f);
    #pragma unroll
    for (int nf = 0; nf < 12; nf++) {
        const int col = nf * 8 + (lane & 3) * 2;
        *(__half2*)(O + baseQ + (long)rA * EMBD + col) =
            __floats2half2_rn(oa[nf][0] * s0, oa[nf][1] * s0);
        *(__half2*)(O + baseQ + (long)(rA + 8) * EMBD + col) =
            __floats2half2_rn(oa[nf][2] * s1, oa[nf][3] * s1);
    }
}

// ---------------- launch ----------------------------------------------------
extern "C" void kernel_launch(void* const* d_in, const int* in_sizes, int n_in,
                              void* d_out, int out_size) {
    const float* x     = (const float*)d_in[0];
    const float* ln1_g = (const float*)d_in[1];
    const float* ln1_b = (const float*)d_in[2];
    const float* wq    = (const float*)d_in[3];
    const float* bq    = (const float*)d_in[4];
    const float* wk    = (const float*)d_in[5];
    const float* bk    = (const float*)d_in[6];
    const float* wv    = (const float*)d_in[7];
    const float* bv    = (const float*)d_in[8];
    const float* wo    = (const float*)d_in[9];
    const float* bo    = (const float*)d_in[10];
    const float* ln2_g = (const float*)d_in[11];
    const float* ln2_b = (const float*)d_in[12];
    const float* w1    = (const float*)d_in[13];
    const float* b1    = (const float*)d_in[14];
    const float* w2    = (const float*)d_in[15];
    const float* b2    = (const float*)d_in[16];

    __half *yh, *qh, *kh, *vT, *oh, *zh, *hh, *wqkvT, *woT, *w1T, *w2T;
    float *x1, *bqkv;
    cudaGetSymbolAddress((void**)&yh,    g_yh);
    cudaGetSymbolAddress((void**)&qh,    g_qh);
    cudaGetSymbolAddress((void**)&kh,    g_kh);
    cudaGetSymbolAddress((void**)&vT,    g_vT);
    cudaGetSymbolAddress((void**)&oh,    g_oh);
    cudaGetSymbolAddress((void**)&zh,    g_zh);
    cudaGetSymbolAddress((void**)&hh,    g_hh);
    cudaGetSymbolAddress((void**)&x1,    g_x1);
    cudaGetSymbolAddress((void**)&wqkvT, g_wqkvT);
    cudaGetSymbolAddress((void**)&bqkv,  g_bqkv);
    cudaGetSymbolAddress((void**)&woT,   g_woT);
    cudaGetSymbolAddress((void**)&w1T,   g_w1T);
    cudaGetSymbolAddress((void**)&w2T,   g_w2T);

    cudaFuncSetAttribute(attn_h,
                         cudaFuncAttributeMaxDynamicSharedMemorySize, ATT_SMEM);
    cudaFuncSetAttribute(gemm_h<1>,
                         cudaFuncAttributeMaxDynamicSharedMemorySize, GMH_SMEM);
    cudaFuncSetAttribute(gemm_h<2>,
                         cudaFuncAttributeMaxDynamicSharedMemorySize, GMH_SMEM);
    cudaFuncSetAttribute(gemm_h<3>,
                         cudaFuncAttributeMaxDynamicSharedMemorySize, GMH_SMEM);

    const dim3 tb(32, 8);
    convT_kernel<<<dim3(EMBD / 32, EMBD / 32), tb>>>(wq, wqkvT, EMBD, EMBD);
    convT_kernel<<<dim3(EMBD / 32, EMBD / 32), tb>>>(wk, wqkvT + EMBD * EMBD, EMBD, EMBD);
    convT_kernel<<<dim3(EMBD / 32, EMBD / 32), tb>>>(wv, wqkvT + 2 * EMBD * EMBD, EMBD, EMBD);
    convT_kernel<<<dim3(EMBD / 32, EMBD / 32), tb>>>(wo, woT, EMBD, EMBD);
    convT_kernel<<<dim3(DFF2 / 32, EMBD / 32), tb>>>(w1, w1T, EMBD, DFF2);
    convT_kernel<<<dim3(EMBD / 32, DFF2 / 32), tb>>>(w2, w2T, DFF2, EMBD);
    bias_cat_kernel<<<3, 256>>>(bq, bk, bv, bqkv);

    // LN1
    ln_kernel<<<TOK, 256>>>(x, ln1_g, ln1_b, yh);
    // fused QKV projection (EPI=3 writes g_qh/g_kh/g_vT directly)
    gemm_h<3><<<dim3(NQKV / 64, TOK / 128), 256, GMH_SMEM>>>(yh, wqkvT, bqkv, nullptr, nullptr, TOK, NQKV, EMBD);
    // attention
    attn_h<<<dim3(SEQ / FBM, NHEAD, NBATCH), 256, ATT_SMEM>>>(qh, kh, vT, oh);
    // output projection + residual (fp32 out)
    gemm_h<1><<<dim3(EMBD / 64, TOK / 128), 256, GMH_SMEM>>>(oh, woT, bo, x, x1, TOK, EMBD, EMBD);
    // LN2
    ln_kernel<<<TOK, 256>>>(x1, ln2_g, ln2_b, zh);
    // FFN
    gemm_h<2><<<dim3(DFF2 / 64, TOK / 128), 256, GMH_SMEM>>>(zh, w1T, b1, nullptr, hh, TOK, DFF2, EMBD);
    gemm_h<1><<<dim3(EMBD / 64, TOK / 128), 256, GMH_SMEM>>>(hh, w2T, b2, x1, d_out, TOK, EMBD, DFF2);
}

// round 8
// speedup vs baseline: 8.1900x; 1.0729x over previous
#include <cuda_runtime.h>
#include <cuda_fp16.h>
#include <math.h>
#include <stdint.h>

#define TOK   8192
#define EMBD  768
#define DFF2  3072
#define NHEAD 8
#define HD    96
#define SEQ   2048
#define NBATCH 4
#define NQKV  2304

// ---------------- scratch (device globals) ----------------------------------
__device__ __half g_yh[TOK * EMBD];
__device__ __half g_qh[TOK * EMBD];
__device__ __half g_kh[TOK * EMBD];
__device__ __half g_vT[TOK * EMBD];     // [b][h][d][seq]
__device__ __half g_oh[TOK * EMBD];
__device__ __half g_zh[TOK * EMBD];
__device__ __half g_hh[TOK * DFF2];
__device__ float  g_x1[TOK * EMBD];
__device__ __half g_wqkvT[NQKV * EMBD]; // [2304][768]: wq|wk|wv transposed
__device__ float  g_bqkv[NQKV];
__device__ __half g_woT[EMBD * EMBD];
__device__ __half g_w1T[DFF2 * EMBD];
__device__ __half g_w2T[EMBD * DFF2];

// ---------------- helpers ----------------------------------------------------
__device__ __forceinline__ void cpasync16(uint32_t saddr, const void* gaddr) {
    asm volatile("cp.async.cg.shared.global [%0], [%1], 16;" :: "r"(saddr), "l"(gaddr));
}
#define CP_COMMIT() asm volatile("cp.async.commit_group;" ::: "memory")

__device__ __forceinline__ uint32_t smem_u32(const void* p) {
    uint32_t a;
    asm("{ .reg .u64 t; cvta.to.shared.u64 t, %1; cvt.u32.u64 %0, t; }"
        : "=r"(a) : "l"(p));
    return a;
}

__device__ __forceinline__ void mma_f16(float* c, const uint32_t* a, const uint32_t* b) {
    asm volatile(
        "mma.sync.aligned.m16n8k16.row.col.f32.f16.f16.f32 "
        "{%0,%1,%2,%3}, {%4,%5,%6,%7}, {%8,%9}, {%0,%1,%2,%3};"
        : "+f"(c[0]), "+f"(c[1]), "+f"(c[2]), "+f"(c[3])
        : "r"(a[0]), "r"(a[1]), "r"(a[2]), "r"(a[3]), "r"(b[0]), "r"(b[1]));
}

__device__ __forceinline__ void ldmx4(uint32_t* r, uint32_t saddr) {
    asm volatile("ldmatrix.sync.aligned.m8n8.x4.shared.b16 {%0,%1,%2,%3}, [%4];"
        : "=r"(r[0]), "=r"(r[1]), "=r"(r[2]), "=r"(r[3]) : "r"(saddr));
}

// ---------------- all weight transposes in ONE kernel ------------------------
__global__ __launch_bounds__(256)
void convT_all(const float* __restrict__ wq, const float* __restrict__ wk,
               const float* __restrict__ wv, const float* __restrict__ wo,
               const float* __restrict__ w1, const float* __restrict__ w2) {
    __shared__ float t[32][33];
    const int bid = blockIdx.x;
    const float* W;
    __half* Wt;
    int K, N, n0, k0;
    if (bid < 2304) {               // four 768x768 matrices, 576 tiles each
        const int seg = bid / 576, tl = bid % 576;
        K = EMBD; N = EMBD;
        if (seg == 0)      { W = wq; Wt = g_wqkvT; }
        else if (seg == 1) { W = wk; Wt = g_wqkvT + EMBD * EMBD; }
        else if (seg == 2) { W = wv; Wt = g_wqkvT + 2 * EMBD * EMBD; }
        else               { W = wo; Wt = g_woT; }
        n0 = (tl % 24) * 32; k0 = (tl / 24) * 32;
    } else if (bid < 4608) {        // w1: 768x3072
        const int tl = bid - 2304;
        K = EMBD; N = DFF2; W = w1; Wt = g_w1T;
        n0 = (tl % 96) * 32; k0 = (tl / 96) * 32;
    } else {                        // w2: 3072x768
        const int tl = bid - 4608;
        K = DFF2; N = EMBD; W = w2; Wt = g_w2T;
        n0 = (tl % 24) * 32; k0 = (tl / 24) * 32;
    }
    const int tx = threadIdx.x, ty = threadIdx.y;   // 32 x 8
    #pragma unroll
    for (int i = 0; i < 32; i += 8)
        t[ty + i][tx] = W[(long)(k0 + ty + i) * N + n0 + tx];
    __syncthreads();
    #pragma unroll
    for (int i = 0; i < 32; i += 8)
        Wt[(long)(n0 + ty + i) * K + k0 + tx] = __float2half(t[tx][ty + i]);
}

__global__ void bias_cat_kernel(const float* bq, const float* bk, const float* bv,
                                float* out) {
    const int i = blockIdx.x * 256 + threadIdx.x;
    if (i < EMBD) { out[i] = bq[i]; out[i + EMBD] = bk[i]; out[i + 2 * EMBD] = bv[i]; }
}

// ---------------- LayerNorm (fp32 in -> fp16 out) ---------------------------
__global__ __launch_bounds__(256)
void ln_kernel(const float* __restrict__ x, const float* __restrict__ g,
               const float* __restrict__ b, __half* __restrict__ y) {
    const int row = blockIdx.x;
    const float* xr = x + (long)row * EMBD;
    const int t = threadIdx.x;
    float v0 = xr[t], v1 = xr[t + 256], v2 = xr[t + 512];
    float s  = v0 + v1 + v2;
    float sq = v0 * v0 + v1 * v1 + v2 * v2;
    #pragma unroll
    for (int o = 16; o; o >>= 1) {
        s  += __shfl_xor_sync(0xffffffffu, s,  o);
        sq += __shfl_xor_sync(0xffffffffu, sq, o);
    }
    __shared__ float sbuf[16];
    const int w = t >> 5, l = t & 31;
    if (l == 0) { sbuf[w] = s; sbuf[w + 8] = sq; }
    __syncthreads();
    float ts = 0.f, tsq = 0.f;
    #pragma unroll
    for (int i = 0; i < 8; i++) { ts += sbuf[i]; tsq += sbuf[8 + i]; }
    const float mu  = ts * (1.0f / EMBD);
    const float var = tsq * (1.0f / EMBD) - mu * mu;
    const float r   = rsqrtf(var + 1e-5f);
    __half* yr = y + (long)row * EMBD;
    yr[t]       = __float2half((v0 - mu) * r * g[t]       + b[t]);
    yr[t + 256] = __float2half((v1 - mu) * r * g[t + 256] + b[t + 256]);
    yr[t + 512] = __float2half((v2 - mu) * r * g[t + 512] + b[t + 512]);
}

// ============ fp16 mma GEMM: tile 128x64, single-sync multistage =============
// EPI: 0 bias(->h), 1 bias+res(->f32), 2 bias+GELU(->h), 3 QKV split epilogue
#define HGK    64
#define HSTR   72
#define A_HB   (128 * HSTR * 2)
#define B_HB   (64 * HSTR * 2)
#define STG_HB (A_HB + B_HB)          // 27648
#define NSTG   4
#define GMH_SMEM (NSTG * STG_HB)      // 110592

__device__ __forceinline__ void ld_stage_h(uint32_t sa,
                                           const __half* __restrict__ A,
                                           const __half* __restrict__ Bt,
                                           int bm, int bn, int K,
                                           int k0, int tid) {
    #pragma unroll
    for (int j = 0; j < 4; j++) {
        const int ch = tid + j * 256;
        const int r = ch >> 3, kc = ch & 7;
        cpasync16(sa + (r * HSTR + kc * 8) * 2,
                  A + (long)(bm + r) * K + k0 + kc * 8);
    }
    const uint32_t sb = sa + A_HB;
    #pragma unroll
    for (int j = 0; j < 2; j++) {
        const int ch = tid + j * 256;
        const int r = ch >> 3, kc = ch & 7;
        cpasync16(sb + (r * HSTR + kc * 8) * 2,
                  Bt + (long)(bn + r) * K + k0 + kc * 8);
    }
}

template <int EPI>
__global__ __launch_bounds__(256, 2)
void gemm_h(const __half* __restrict__ A, const __half* __restrict__ Bt,
            const float* __restrict__ bias, const float* __restrict__ res,
            void* __restrict__ Cout, int M, int N, int K) {
    extern __shared__ __half smh[];
    const uint32_t sbase = smem_u32(smh);

    const int tid  = threadIdx.x;
    const int lane = tid & 31;
    const int wid  = tid >> 5;
    const int bm = blockIdx.y * 128;
    const int bn = blockIdx.x * 64;
    const int wm = (wid & 3) * 32;
    const int wn = (wid >> 2) * 32;

    const int aRow = wm + (lane & 15);
    const int aK   = (lane >> 4) * 8;
    const int bRow = wn + ((lane >> 4) & 1) * 8 + (lane & 7);
    const int bK   = ((lane >> 3) & 1) * 8;

    float acc[2][4][4];
    #pragma unroll
    for (int mi = 0; mi < 2; mi++)
        #pragma unroll
        for (int ni = 0; ni < 4; ni++)
            #pragma unroll
            for (int u = 0; u < 4; u++) acc[mi][ni][u] = 0.f;

    const int nkt = K / HGK;
    // prologue: NSTG-1 stages in flight
    #pragma unroll
    for (int p = 0; p < NSTG - 1; p++) {
        if (p < nkt) ld_stage_h(sbase + p * STG_HB, A, Bt, bm, bn, K, p * HGK, tid);
        CP_COMMIT();
    }

    int bufr = 0, bufw = NSTG - 1;
    for (int kt = 0; kt < nkt; kt++) {
        asm volatile("cp.async.wait_group %0;" :: "n"(NSTG - 2) : "memory");
        __syncthreads();   // stage bufr ready; buffer bufw free (computed kt-1)

        const int next = kt + NSTG - 1;
        if (next < nkt)
            ld_stage_h(sbase + bufw * STG_HB, A, Bt, bm, bn, K, next * HGK, tid);
        CP_COMMIT();

        const uint32_t fA_u = sbase + bufr * STG_HB;
        const uint32_t fB_u = fA_u + A_HB;
        #pragma unroll
        for (int ks = 0; ks < 4; ks++) {
            uint32_t af[2][4];
            #pragma unroll
            for (int mi = 0; mi < 2; mi++)
                ldmx4(af[mi], fA_u + ((aRow + mi * 16) * HSTR + ks * 16 + aK) * 2);
            uint32_t bb[2][4];
            #pragma unroll
            for (int nj = 0; nj < 2; nj++)
                ldmx4(bb[nj], fB_u + ((bRow + nj * 16) * HSTR + ks * 16 + bK) * 2);
            #pragma unroll
            for (int mi = 0; mi < 2; mi++)
                #pragma unroll
                for (int nj = 0; nj < 2; nj++) {
                    mma_f16(acc[mi][nj * 2 + 0], af[mi], &bb[nj][0]);
                    mma_f16(acc[mi][nj * 2 + 1], af[mi], &bb[nj][2]);
                }
        }
        bufr = (bufr + 1 == NSTG) ? 0 : bufr + 1;
        bufw = (bufw + 1 == NSTG) ? 0 : bufw + 1;
    }

    const int erow = bm + wm + (lane >> 2);
    const int ecol = bn + wn + (lane & 3) * 2;
    #pragma unroll
    for (int mi = 0; mi < 2; mi++) {
        #pragma unroll
        for (int half = 0; half < 2; half++) {
            const long r = erow + mi * 16 + half * 8;
            #pragma unroll
            for (int ni = 0; ni < 4; ni++) {
                const int c = ecol + ni * 8;
                float v0 = acc[mi][ni][half * 2 + 0] + bias[c];
                float v1 = acc[mi][ni][half * 2 + 1] + bias[c + 1];
                if (EPI == 2) {
                    v0 = 0.5f * v0 * (1.0f + erff(v0 * 0.70710678118654752f));
                    v1 = 0.5f * v1 * (1.0f + erff(v1 * 0.70710678118654752f));
                }
                if (EPI == 1) {
                    v0 += res[r * N + c];
                    v1 += res[r * N + c + 1];
                }
                if (EPI == 3) {
                    if (c < EMBD) {
                        *(__half2*)&g_qh[r * EMBD + c] = __floats2half2_rn(v0, v1);
                    } else if (c < 2 * EMBD) {
                        *(__half2*)&g_kh[r * EMBD + c - EMBD] = __floats2half2_rn(v0, v1);
                    } else {
                        const int cc = c - 2 * EMBD;
                        const int bb2 = (int)(r >> 11), srow = (int)(r & 2047);
                        g_vT[((long)(bb2 * NHEAD + cc / HD) * HD + (cc % HD)) * SEQ + srow] = __float2half(v0);
                        g_vT[((long)(bb2 * NHEAD + (cc + 1) / HD) * HD + ((cc + 1) % HD)) * SEQ + srow] = __float2half(v1);
                    }
                } else if (EPI == 1) {
                    *(float2*)((float*)Cout + r * N + c) = make_float2(v0, v1);
                } else {
                    *(__half2*)((__half*)Cout + r * N + c) = __floats2half2_rn(v0, v1);
                }
            }
        }
    }
}

// =================== fp16 flash attention (2 CTA/SM, single-sync) ============
#define FBM    128
#define FBN    64
#define QSTR_H 104
#define KSTR_H 104
#define VSTR_H 72
#define PSTR_H 72
#define SQ_H   (FBM * QSTR_H)
#define SP_H   (FBM * PSTR_H)
#define KV_H   (FBN * KSTR_H + HD * VSTR_H)
#define ATT_SMEM ((SQ_H + SP_H + 2 * KV_H) * 2)

__device__ __forceinline__ void attn_ld_kv_h(uint32_t sk, uint32_t sv,
                                             const __half* __restrict__ K,
                                             const __half* __restrict__ VT,
                                             long baseKV, long baseVT,
                                             int kt, int tid) {
    #pragma unroll
    for (int j = 0; j < 3; j++) {
        const int ch = tid + j * 256;
        const int r = ch / 12, c = ch % 12;
        cpasync16(sk + (r * KSTR_H + c * 8) * 2,
                  K + baseKV + (long)(kt * FBN + r) * EMBD + c * 8);
    }
    #pragma unroll
    for (int j = 0; j < 3; j++) {
        const int ch = tid + j * 256;
        const int d = ch >> 3, sc = ch & 7;
        cpasync16(sv + (d * VSTR_H + sc * 8) * 2,
                  VT + baseVT + (long)d * SEQ + kt * FBN + sc * 8);
    }
}

__global__ __launch_bounds__(256, 2)
void attn_h(const __half* __restrict__ Q, const __half* __restrict__ K,
            const __half* __restrict__ VT, __half* __restrict__ O) {
    extern __shared__ __half smh[];
    __half* sQ = smh;
    __half* sP = sQ + SQ_H;
    __half* sKV = sP + SP_H;
    const uint32_t sQ_u  = smem_u32(sQ);
    const uint32_t sP_u  = smem_u32(sP);
    const uint32_t skv_u = smem_u32(sKV);

    const int b  = blockIdx.z;
    const int h  = blockIdx.y;
    const int qt = blockIdx.x;
    const int tid  = threadIdx.x;
    const int lane = tid & 31;
    const int wid  = tid >> 5;

    const long baseQ  = ((long)(b * SEQ + qt * FBM)) * EMBD + h * HD;
    const long baseKV = ((long)(b * SEQ)) * EMBD + h * HD;
    const long baseVT = (long)(b * NHEAD + h) * HD * SEQ;

    // prologue: Q tile + KV stage 0 in one cp.async group
    for (int i = tid; i < FBM * 12; i += 256) {
        const int r = i / 12, c = i % 12;
        cpasync16(sQ_u + (r * QSTR_H + c * 8) * 2,
                  Q + baseQ + (long)r * EMBD + c * 8);
    }
    attn_ld_kv_h(skv_u, skv_u + FBN * KSTR_H * 2, K, VT, baseKV, baseVT, 0, tid);
    CP_COMMIT();

    const int aRow = wid * 16 + (lane & 15);
    const int aK   = (lane >> 4) * 8;
    const int bRow = ((lane >> 4) & 1) * 8 + (lane & 7);
    const int bK   = ((lane >> 3) & 1) * 8;
    const int rA = wid * 16 + (lane >> 2);

    float m0 = -1e30f, m1 = -1e30f, l0 = 0.f, l1 = 0.f;
    float oa[12][4];
    #pragma unroll
    for (int nf = 0; nf < 12; nf++)
        #pragma unroll
        for (int u = 0; u < 4; u++) oa[nf][u] = 0.f;

    const int NIT = SEQ / FBN;
    for (int it = 0; it < NIT; it++) {
        asm volatile("cp.async.wait_group 0;" ::: "memory");
        __syncthreads();   // stage it ready; other buffer free (computed it-1)

        if (it + 1 < NIT) {
            const uint32_t sn = skv_u + ((it + 1) & 1) * KV_H * 2;
            attn_ld_kv_h(sn, sn + FBN * KSTR_H * 2, K, VT, baseKV, baseVT, it + 1, tid);
        }
        CP_COMMIT();

        const uint32_t fK_u = skv_u + (it & 1) * KV_H * 2;
        const uint32_t fV_u = fK_u + FBN * KSTR_H * 2;

        // ---- S = Q K^T ----
        float sc[8][4];
        #pragma unroll
        for (int nf = 0; nf < 8; nf++)
            #pragma unroll
            for (int u = 0; u < 4; u++) sc[nf][u] = 0.f;

        #pragma unroll
        for (int ks = 0; ks < 6; ks++) {
            uint32_t af[4];
            ldmx4(af, sQ_u + (aRow * QSTR_H + ks * 16 + aK) * 2);
            #pragma unroll
            for (int nj = 0; nj < 4; nj++) {
                uint32_t bb[4];
                ldmx4(bb, fK_u + ((bRow + nj * 16) * KSTR_H + ks * 16 + bK) * 2);
                mma_f16(sc[nj * 2 + 0], af, &bb[0]);
                mma_f16(sc[nj * 2 + 1], af, &bb[2]);
            }
        }

        // ---- online softmax ----
        float t0 = -1e30f, t1 = -1e30f;
        #pragma unroll
        for (int nf = 0; nf < 8; nf++) {
            t0 = fmaxf(t0, fmaxf(sc[nf][0], sc[nf][1]));
            t1 = fmaxf(t1, fmaxf(sc[nf][2], sc[nf][3]));
        }
        t0 = fmaxf(t0, __shfl_xor_sync(0xffffffffu, t0, 1));
        t0 = fmaxf(t0, __shfl_xor_sync(0xffffffffu, t0, 2));
        t1 = fmaxf(t1, __shfl_xor_sync(0xffffffffu, t1, 1));
        t1 = fmaxf(t1, __shfl_xor_sync(0xffffffffu, t1, 2));
        const float mn0 = fmaxf(m0, t0), mn1 = fmaxf(m1, t1);
        const float cr0 = __expf(m0 - mn0), cr1 = __expf(m1 - mn1);
        float rs0 = 0.f, rs1 = 0.f;
        #pragma unroll
        for (int nf = 0; nf < 8; nf++) {
            const float p00 = __expf(sc[nf][0] - mn0);
            const float p01 = __expf(sc[nf][1] - mn0);
            const float p10 = __expf(sc[nf][2] - mn1);
            const float p11 = __expf(sc[nf][3] - mn1);
            rs0 += p00 + p01; rs1 += p10 + p11;
            const int col = nf * 8 + (lane & 3) * 2;
            *(__half2*)&sP[rA * PSTR_H + col]       = __floats2half2_rn(p00, p01);
            *(__half2*)&sP[(rA + 8) * PSTR_H + col] = __floats2half2_rn(p10, p11);
        }
        rs0 += __shfl_xor_sync(0xffffffffu, rs0, 1);
        rs0 += __shfl_xor_sync(0xffffffffu, rs0, 2);
        rs1 += __shfl_xor_sync(0xffffffffu, rs1, 1);
        rs1 += __shfl_xor_sync(0xffffffffu, rs1, 2);
        l0 = l0 * cr0 + rs0; m0 = mn0;
        l1 = l1 * cr1 + rs1; m1 = mn1;
        #pragma unroll
        for (int nf = 0; nf < 12; nf++) {
            oa[nf][0] *= cr0; oa[nf][1] *= cr0;
            oa[nf][2] *= cr1; oa[nf][3] *= cr1;
        }
        __syncwarp();

        // ---- O += P V ----
        #pragma unroll
        for (int ks = 0; ks < 4; ks++) {
            uint32_t af[4];
            ldmx4(af, sP_u + (aRow * PSTR_H + ks * 16 + aK) * 2);
            #pragma unroll
            for (int nj = 0; nj < 6; nj++) {
                uint32_t bb[4];
                ldmx4(bb, fV_u + ((bRow + nj * 16) * VSTR_H + ks * 16 + bK) * 2);
                mma_f16(oa[nj * 2 + 0], af, &bb[0]);
                mma_f16(oa[nj * 2 + 1], af, &bb[2]);
            }
        }
        __syncwarp();
    }

    const float s0 = 1.0f / (l0 * 27.712812921102035f);
    const float s1 = 1.0f / (l1 * 27.712812921102035f);
    #pragma unroll
    for (int nf = 0; nf < 12; nf++) {
        const int col = nf * 8 + (lane & 3) * 2;
        *(__half2*)(O + baseQ + (long)rA * EMBD + col) =
            __floats2half2_rn(oa[nf][0] * s0, oa[nf][1] * s0);
        *(__half2*)(O + baseQ + (long)(rA + 8) * EMBD + col) =
            __floats2half2_rn(oa[nf][2] * s1, oa[nf][3] * s1);
    }
}

// ---------------- launch ----------------------------------------------------
extern "C" void kernel_launch(void* const* d_in, const int* in_sizes, int n_in,
                              void* d_out, int out_size) {
    const float* x     = (const float*)d_in[0];
    const float* ln1_g = (const float*)d_in[1];
    const float* ln1_b = (const float*)d_in[2];
    const float* wq    = (const float*)d_in[3];
    const float* bq    = (const float*)d_in[4];
    const float* wk    = (const float*)d_in[5];
    const float* bk    = (const float*)d_in[6];
    const float* wv    = (const float*)d_in[7];
    const float* bv    = (const float*)d_in[8];
    const float* wo    = (const float*)d_in[9];
    const float* bo    = (const float*)d_in[10];
    const float* ln2_g = (const float*)d_in[11];
    const float* ln2_b = (const float*)d_in[12];
    const float* w1    = (const float*)d_in[13];
    const float* b1    = (const float*)d_in[14];
    const float* w2    = (const float*)d_in[15];
    const float* b2    = (const float*)d_in[16];

    __half *yh, *qh, *kh, *vT, *oh, *zh, *hh, *wqkvT, *woT, *w1T, *w2T;
    float *x1, *bqkv;
    cudaGetSymbolAddress((void**)&yh,    g_yh);
    cudaGetSymbolAddress((void**)&qh,    g_qh);
    cudaGetSymbolAddress((void**)&kh,    g_kh);
    cudaGetSymbolAddress((void**)&vT,    g_vT);
    cudaGetSymbolAddress((void**)&oh,    g_oh);
    cudaGetSymbolAddress((void**)&zh,    g_zh);
    cudaGetSymbolAddress((void**)&hh,    g_hh);
    cudaGetSymbolAddress((void**)&x1,    g_x1);
    cudaGetSymbolAddress((void**)&wqkvT, g_wqkvT);
    cudaGetSymbolAddress((void**)&bqkv,  g_bqkv);
    cudaGetSymbolAddress((void**)&woT,   g_woT);
    cudaGetSymbolAddress((void**)&w1T,   g_w1T);
    cudaGetSymbolAddress((void**)&w2T,   g_w2T);

    cudaFuncSetAttribute(attn_h,
                         cudaFuncAttributeMaxDynamicSharedMemorySize, ATT_SMEM);
    cudaFuncSetAttribute(gemm_h<1>,
                         cudaFuncAttributeMaxDynamicSharedMemorySize, GMH_SMEM);
    cudaFuncSetAttribute(gemm_h<2>,
                         cudaFuncAttributeMaxDynamicSharedMemorySize, GMH_SMEM);
    cudaFuncSetAttribute(gemm_h<3>,
                         cudaFuncAttributeMaxDynamicSharedMemorySize, GMH_SMEM);

    // all weight transposes in one launch
    convT_all<<<6912, dim3(32, 8)>>>(wq, wk, wv, wo, w1, w2);
    bias_cat_kernel<<<3, 256>>>(bq, bk, bv, bqkv);

    // LN1
    ln_kernel<<<TOK, 256>>>(x, ln1_g, ln1_b, yh);
    // fused QKV projection (EPI=3 writes g_qh/g_kh/g_vT directly)
    gemm_h<3><<<dim3(NQKV / 64, TOK / 128), 256, GMH_SMEM>>>(yh, wqkvT, bqkv, nullptr, nullptr, TOK, NQKV, EMBD);
    // attention
    attn_h<<<dim3(SEQ / FBM, NHEAD, NBATCH), 256, ATT_SMEM>>>(qh, kh, vT, oh);
    // output projection + residual (fp32 out)
    gemm_h<1><<<dim3(EMBD / 64, TOK / 128), 256, GMH_SMEM>>>(oh, woT, bo, x, x1, TOK, EMBD, EMBD);
    // LN2
    ln_kernel<<<TOK, 256>>>(x1, ln2_g, ln2_b, zh);
    // FFN
    gemm_h<2><<<dim3(DFF2 / 64, TOK / 128), 256, GMH_SMEM>>>(zh, w1T, b1, nullptr, hh, TOK, DFF2, EMBD);
    gemm_h<1><<<dim3(EMBD / 64, TOK / 128), 256, GMH_SMEM>>>(hh, w2T, b2, x1, d_out, TOK, EMBD, DFF2);
}

// round 9
// speedup vs baseline: 9.1340x; 1.1153x over previous
#include <cuda_runtime.h>
#include <cuda_fp16.h>
#include <math.h>
#include <stdint.h>

#define TOK   8192
#define EMBD  768
#define DFF2  3072
#define NHEAD 8
#define HD    96
#define SEQ   2048
#define NBATCH 4
#define NQKV  2304

// ---------------- scratch (device globals) ----------------------------------
__device__ __half g_yh[TOK * EMBD];
__device__ __half g_qh[TOK * EMBD];
__device__ __half g_kh[TOK * EMBD];
__device__ __half g_vT[TOK * EMBD];     // [b][h][d][seq]
__device__ __half g_oh[TOK * EMBD];
__device__ __half g_zh[TOK * EMBD];
__device__ __half g_hh[TOK * DFF2];
__device__ float  g_x1[TOK * EMBD];
__device__ __half g_wqkvT[NQKV * EMBD]; // [2304][768]: wq|wk|wv transposed
__device__ float  g_bqkv[NQKV];
__device__ __half g_woT[EMBD * EMBD];
__device__ __half g_w1T[DFF2 * EMBD];
__device__ __half g_w2T[EMBD * DFF2];

// ---------------- helpers ----------------------------------------------------
__device__ __forceinline__ void cpasync16(uint32_t saddr, const void* gaddr) {
    asm volatile("cp.async.cg.shared.global [%0], [%1], 16;" :: "r"(saddr), "l"(gaddr));
}
#define CP_COMMIT() asm volatile("cp.async.commit_group;" ::: "memory")

__device__ __forceinline__ uint32_t smem_u32(const void* p) {
    uint32_t a;
    asm("{ .reg .u64 t; cvta.to.shared.u64 t, %1; cvt.u32.u64 %0, t; }"
        : "=r"(a) : "l"(p));
    return a;
}

__device__ __forceinline__ void mma_f16(float* c, const uint32_t* a, const uint32_t* b) {
    asm volatile(
        "mma.sync.aligned.m16n8k16.row.col.f32.f16.f16.f32 "
        "{%0,%1,%2,%3}, {%4,%5,%6,%7}, {%8,%9}, {%0,%1,%2,%3};"
        : "+f"(c[0]), "+f"(c[1]), "+f"(c[2]), "+f"(c[3])
        : "r"(a[0]), "r"(a[1]), "r"(a[2]), "r"(a[3]), "r"(b[0]), "r"(b[1]));
}

__device__ __forceinline__ void ldmx4(uint32_t* r, uint32_t saddr) {
    asm volatile("ldmatrix.sync.aligned.m8n8.x4.shared.b16 {%0,%1,%2,%3}, [%4];"
        : "=r"(r[0]), "=r"(r[1]), "=r"(r[2]), "=r"(r[3]) : "r"(saddr));
}

// ---------------- all weight transposes in ONE kernel ------------------------
__global__ __launch_bounds__(256)
void convT_all(const float* __restrict__ wq, const float* __restrict__ wk,
               const float* __restrict__ wv, const float* __restrict__ wo,
               const float* __restrict__ w1, const float* __restrict__ w2) {
    __shared__ float t[32][33];
    const int bid = blockIdx.x;
    const float* W;
    __half* Wt;
    int K, N, n0, k0;
    if (bid < 2304) {
        const int seg = bid / 576, tl = bid % 576;
        K = EMBD; N = EMBD;
        if (seg == 0)      { W = wq; Wt = g_wqkvT; }
        else if (seg == 1) { W = wk; Wt = g_wqkvT + EMBD * EMBD; }
        else if (seg == 2) { W = wv; Wt = g_wqkvT + 2 * EMBD * EMBD; }
        else               { W = wo; Wt = g_woT; }
        n0 = (tl % 24) * 32; k0 = (tl / 24) * 32;
    } else if (bid < 4608) {
        const int tl = bid - 2304;
        K = EMBD; N = DFF2; W = w1; Wt = g_w1T;
        n0 = (tl % 96) * 32; k0 = (tl / 96) * 32;
    } else {
        const int tl = bid - 4608;
        K = DFF2; N = EMBD; W = w2; Wt = g_w2T;
        n0 = (tl % 24) * 32; k0 = (tl / 24) * 32;
    }
    const int tx = threadIdx.x, ty = threadIdx.y;
    #pragma unroll
    for (int i = 0; i < 32; i += 8)
        t[ty + i][tx] = W[(long)(k0 + ty + i) * N + n0 + tx];
    __syncthreads();
    #pragma unroll
    for (int i = 0; i < 32; i += 8)
        Wt[(long)(n0 + ty + i) * K + k0 + tx] = __float2half(t[tx][ty + i]);
}

__global__ void bias_cat_kernel(const float* bq, const float* bk, const float* bv,
                                float* out) {
    const int i = blockIdx.x * 256 + threadIdx.x;
    if (i < EMBD) { out[i] = bq[i]; out[i + EMBD] = bk[i]; out[i + 2 * EMBD] = bv[i]; }
}

// ---------------- LayerNorm (fp32 in -> fp16 out) ---------------------------
__global__ __launch_bounds__(256)
void ln_kernel(const float* __restrict__ x, const float* __restrict__ g,
               const float* __restrict__ b, __half* __restrict__ y) {
    const int row = blockIdx.x;
    const float* xr = x + (long)row * EMBD;
    const int t = threadIdx.x;
    float v0 = xr[t], v1 = xr[t + 256], v2 = xr[t + 512];
    float s  = v0 + v1 + v2;
    float sq = v0 * v0 + v1 * v1 + v2 * v2;
    #pragma unroll
    for (int o = 16; o; o >>= 1) {
        s  += __shfl_xor_sync(0xffffffffu, s,  o);
        sq += __shfl_xor_sync(0xffffffffu, sq, o);
    }
    __shared__ float sbuf[16];
    const int w = t >> 5, l = t & 31;
    if (l == 0) { sbuf[w] = s; sbuf[w + 8] = sq; }
    __syncthreads();
    float ts = 0.f, tsq = 0.f;
    #pragma unroll
    for (int i = 0; i < 8; i++) { ts += sbuf[i]; tsq += sbuf[8 + i]; }
    const float mu  = ts * (1.0f / EMBD);
    const float var = tsq * (1.0f / EMBD) - mu * mu;
    const float r   = rsqrtf(var + 1e-5f);
    __half* yr = y + (long)row * EMBD;
    yr[t]       = __float2half((v0 - mu) * r * g[t]       + b[t]);
    yr[t + 256] = __float2half((v1 - mu) * r * g[t + 256] + b[t + 256]);
    yr[t + 512] = __float2half((v2 - mu) * r * g[t + 512] + b[t + 512]);
}

// ====== fp16 mma GEMM: CTA tile 128x128, warptile 32x64, single-sync =========
// EPI: 0 bias(->h), 1 bias+res(->f32), 2 bias+GELU(->h), 3 QKV split epilogue
#define HGK    64
#define HSTR   72
#define A_HB   (128 * HSTR * 2)       // 18432
#define B_HB   (128 * HSTR * 2)       // 18432
#define STG_HB (A_HB + B_HB)          // 36864
#define NSTG   3
#define GMH_SMEM (NSTG * STG_HB)      // 110592

__device__ __forceinline__ void ld_stage_h(uint32_t sa,
                                           const __half* __restrict__ A,
                                           const __half* __restrict__ Bt,
                                           int bm, int bn, int K,
                                           int k0, int tid) {
    #pragma unroll
    for (int j = 0; j < 4; j++) {
        const int ch = tid + j * 256;
        const int r = ch >> 3, kc = ch & 7;
        cpasync16(sa + (r * HSTR + kc * 8) * 2,
                  A + (long)(bm + r) * K + k0 + kc * 8);
    }
    const uint32_t sb = sa + A_HB;
    #pragma unroll
    for (int j = 0; j < 4; j++) {
        const int ch = tid + j * 256;
        const int r = ch >> 3, kc = ch & 7;
        cpasync16(sb + (r * HSTR + kc * 8) * 2,
                  Bt + (long)(bn + r) * K + k0 + kc * 8);
    }
}

template <int EPI>
__global__ __launch_bounds__(256, 2)
void gemm_h(const __half* __restrict__ A, const __half* __restrict__ Bt,
            const float* __restrict__ bias, const float* __restrict__ res,
            void* __restrict__ Cout, int M, int N, int K) {
    extern __shared__ __half smh[];
    const uint32_t sbase = smem_u32(smh);

    const int tid  = threadIdx.x;
    const int lane = tid & 31;
    const int wid  = tid >> 5;
    const int bm = blockIdx.y * 128;
    const int bn = blockIdx.x * 128;
    const int wm = (wid & 3) * 32;       // 4 M positions
    const int wn = (wid >> 2) * 64;      // 2 N positions, 64 wide

    const int aRow = wm + (lane & 15);
    const int aK   = (lane >> 4) * 8;
    const int bRow = wn + ((lane >> 4) & 1) * 8 + (lane & 7);
    const int bK   = ((lane >> 3) & 1) * 8;

    float acc[2][8][4];
    #pragma unroll
    for (int mi = 0; mi < 2; mi++)
        #pragma unroll
        for (int ni = 0; ni < 8; ni++)
            #pragma unroll
            for (int u = 0; u < 4; u++) acc[mi][ni][u] = 0.f;

    const int nkt = K / HGK;
    #pragma unroll
    for (int p = 0; p < NSTG - 1; p++) {
        if (p < nkt) ld_stage_h(sbase + p * STG_HB, A, Bt, bm, bn, K, p * HGK, tid);
        CP_COMMIT();
    }

    int bufr = 0, bufw = NSTG - 1;
    for (int kt = 0; kt < nkt; kt++) {
        asm volatile("cp.async.wait_group %0;" :: "n"(NSTG - 2) : "memory");
        __syncthreads();

        const int next = kt + NSTG - 1;
        if (next < nkt)
            ld_stage_h(sbase + bufw * STG_HB, A, Bt, bm, bn, K, next * HGK, tid);
        CP_COMMIT();

        const uint32_t fA_u = sbase + bufr * STG_HB;
        const uint32_t fB_u = fA_u + A_HB;
        #pragma unroll
        for (int ks = 0; ks < 4; ks++) {
            uint32_t af[2][4];
            #pragma unroll
            for (int mi = 0; mi < 2; mi++)
                ldmx4(af[mi], fA_u + ((aRow + mi * 16) * HSTR + ks * 16 + aK) * 2);
            #pragma unroll
            for (int nj = 0; nj < 4; nj++) {
                uint32_t bb[4];
                ldmx4(bb, fB_u + ((bRow + nj * 16) * HSTR + ks * 16 + bK) * 2);
                #pragma unroll
                for (int mi = 0; mi < 2; mi++) {
                    mma_f16(acc[mi][nj * 2 + 0], af[mi], &bb[0]);
                    mma_f16(acc[mi][nj * 2 + 1], af[mi], &bb[2]);
                }
            }
        }
        bufr = (bufr + 1 == NSTG) ? 0 : bufr + 1;
        bufw = (bufw + 1 == NSTG) ? 0 : bufw + 1;
    }

    const int erow = bm + wm + (lane >> 2);
    const int ecol = bn + wn + (lane & 3) * 2;
    #pragma unroll
    for (int mi = 0; mi < 2; mi++) {
        #pragma unroll
        for (int half = 0; half < 2; half++) {
            const long r = erow + mi * 16 + half * 8;
            #pragma unroll
            for (int ni = 0; ni < 8; ni++) {
                const int c = ecol + ni * 8;
                float v0 = acc[mi][ni][half * 2 + 0] + bias[c];
                float v1 = acc[mi][ni][half * 2 + 1] + bias[c + 1];
                if (EPI == 2) {
                    v0 = 0.5f * v0 * (1.0f + erff(v0 * 0.70710678118654752f));
                    v1 = 0.5f * v1 * (1.0f + erff(v1 * 0.70710678118654752f));
                }
                if (EPI == 1) {
                    v0 += res[r * N + c];
                    v1 += res[r * N + c + 1];
                }
                if (EPI == 3) {
                    if (c < EMBD) {
                        *(__half2*)&g_qh[r * EMBD + c] = __floats2half2_rn(v0, v1);
                    } else if (c < 2 * EMBD) {
                        *(__half2*)&g_kh[r * EMBD + c - EMBD] = __floats2half2_rn(v0, v1);
                    } else {
                        const int cc = c - 2 * EMBD;
                        const int bb2 = (int)(r >> 11), srow = (int)(r & 2047);
                        g_vT[((long)(bb2 * NHEAD + cc / HD) * HD + (cc % HD)) * SEQ + srow] = __float2half(v0);
                        g_vT[((long)(bb2 * NHEAD + (cc + 1) / HD) * HD + ((cc + 1) % HD)) * SEQ + srow] = __float2half(v1);
                    }
                } else if (EPI == 1) {
                    *(float2*)((float*)Cout + r * N + c) = make_float2(v0, v1);
                } else {
                    *(__half2*)((__half*)Cout + r * N + c) = __floats2half2_rn(v0, v1);
                }
            }
        }
    }
}

// =================== fp16 flash attention (2 CTA/SM, single-sync) ============
#define FBM    128
#define FBN    64
#define QSTR_H 104
#define KSTR_H 104
#define VSTR_H 72
#define PSTR_H 72
#define SQ_H   (FBM * QSTR_H)
#define SP_H   (FBM * PSTR_H)
#define KV_H   (FBN * KSTR_H + HD * VSTR_H)
#define ATT_SMEM ((SQ_H + SP_H + 2 * KV_H) * 2)

__device__ __forceinline__ void attn_ld_kv_h(uint32_t sk, uint32_t sv,
                                             const __half* __restrict__ K,
                                             const __half* __restrict__ VT,
                                             long baseKV, long baseVT,
                                             int kt, int tid) {
    #pragma unroll
    for (int j = 0; j < 3; j++) {
        const int ch = tid + j * 256;
        const int r = ch / 12, c = ch % 12;
        cpasync16(sk + (r * KSTR_H + c * 8) * 2,
                  K + baseKV + (long)(kt * FBN + r) * EMBD + c * 8);
    }
    #pragma unroll
    for (int j = 0; j < 3; j++) {
        const int ch = tid + j * 256;
        const int d = ch >> 3, sc = ch & 7;
        cpasync16(sv + (d * VSTR_H + sc * 8) * 2,
                  VT + baseVT + (long)d * SEQ + kt * FBN + sc * 8);
    }
}

__global__ __launch_bounds__(256, 2)
void attn_h(const __half* __restrict__ Q, const __half* __restrict__ K,
            const __half* __restrict__ VT, __half* __restrict__ O) {
    extern __shared__ __half smh[];
    __half* sQ = smh;
    __half* sP = sQ + SQ_H;
    __half* sKV = sP + SP_H;
    const uint32_t sQ_u  = smem_u32(sQ);
    const uint32_t sP_u  = smem_u32(sP);
    const uint32_t skv_u = smem_u32(sKV);

    const int b  = blockIdx.z;
    const int h  = blockIdx.y;
    const int qt = blockIdx.x;
    const int tid  = threadIdx.x;
    const int lane = tid & 31;
    const int wid  = tid >> 5;

    const long baseQ  = ((long)(b * SEQ + qt * FBM)) * EMBD + h * HD;
    const long baseKV = ((long)(b * SEQ)) * EMBD + h * HD;
    const long baseVT = (long)(b * NHEAD + h) * HD * SEQ;

    for (int i = tid; i < FBM * 12; i += 256) {
        const int r = i / 12, c = i % 12;
        cpasync16(sQ_u + (r * QSTR_H + c * 8) * 2,
                  Q + baseQ + (long)r * EMBD + c * 8);
    }
    attn_ld_kv_h(skv_u, skv_u + FBN * KSTR_H * 2, K, VT, baseKV, baseVT, 0, tid);
    CP_COMMIT();

    const int aRow = wid * 16 + (lane & 15);
    const int aK   = (lane >> 4) * 8;
    const int bRow = ((lane >> 4) & 1) * 8 + (lane & 7);
    const int bK   = ((lane >> 3) & 1) * 8;
    const int rA = wid * 16 + (lane >> 2);

    float m0 = -1e30f, m1 = -1e30f, l0 = 0.f, l1 = 0.f;
    float oa[12][4];
    #pragma unroll
    for (int nf = 0; nf < 12; nf++)
        #pragma unroll
        for (int u = 0; u < 4; u++) oa[nf][u] = 0.f;

    const int NIT = SEQ / FBN;
    for (int it = 0; it < NIT; it++) {
        asm volatile("cp.async.wait_group 0;" ::: "memory");
        __syncthreads();

        if (it + 1 < NIT) {
            const uint32_t sn = skv_u + ((it + 1) & 1) * KV_H * 2;
            attn_ld_kv_h(sn, sn + FBN * KSTR_H * 2, K, VT, baseKV, baseVT, it + 1, tid);
        }
        CP_COMMIT();

        const uint32_t fK_u = skv_u + (it & 1) * KV_H * 2;
        const uint32_t fV_u = fK_u + FBN * KSTR_H * 2;

        float sc[8][4];
        #pragma unroll
        for (int nf = 0; nf < 8; nf++)
            #pragma unroll
            for (int u = 0; u < 4; u++) sc[nf][u] = 0.f;

        #pragma unroll
        for (int ks = 0; ks < 6; ks++) {
            uint32_t af[4];
            ldmx4(af, sQ_u + (aRow * QSTR_H + ks * 16 + aK) * 2);
            #pragma unroll
            for (int nj = 0; nj < 4; nj++) {
                uint32_t bb[4];
                ldmx4(bb, fK_u + ((bRow + nj * 16) * KSTR_H + ks * 16 + bK) * 2);
                mma_f16(sc[nj * 2 + 0], af, &bb[0]);
                mma_f16(sc[nj * 2 + 1], af, &bb[2]);
            }
        }

        float t0 = -1e30f, t1 = -1e30f;
        #pragma unroll
        for (int nf = 0; nf < 8; nf++) {
            t0 = fmaxf(t0, fmaxf(sc[nf][0], sc[nf][1]));
            t1 = fmaxf(t1, fmaxf(sc[nf][2], sc[nf][3]));
        }
        t0 = fmaxf(t0, __shfl_xor_sync(0xffffffffu, t0, 1));
        t0 = fmaxf(t0, __shfl_xor_sync(0xffffffffu, t0, 2));
        t1 = fmaxf(t1, __shfl_xor_sync(0xffffffffu, t1, 1));
        t1 = fmaxf(t1, __shfl_xor_sync(0xffffffffu, t1, 2));
        const float mn0 = fmaxf(m0, t0), mn1 = fmaxf(m1, t1);
        const float cr0 = __expf(m0 - mn0), cr1 = __expf(m1 - mn1);
        float rs0 = 0.f, rs1 = 0.f;
        #pragma unroll
        for (int nf = 0; nf < 8; nf++) {
            const float p00 = __expf(sc[nf][0] - mn0);
            const float p01 = __expf(sc[nf][1] - mn0);
            const float p10 = __expf(sc[nf][2] - mn1);
            const float p11 = __expf(sc[nf][3] - mn1);
            rs0 += p00 + p01; rs1 += p10 + p11;
            const int col = nf * 8 + (lane & 3) * 2;
            *(__half2*)&sP[rA * PSTR_H + col]       = __floats2half2_rn(p00, p01);
            *(__half2*)&sP[(rA + 8) * PSTR_H + col] = __floats2half2_rn(p10, p11);
        }
        rs0 += __shfl_xor_sync(0xffffffffu, rs0, 1);
        rs0 += __shfl_xor_sync(0xffffffffu, rs0, 2);
        rs1 += __shfl_xor_sync(0xffffffffu, rs1, 1);
        rs1 += __shfl_xor_sync(0xffffffffu, rs1, 2);
        l0 = l0 * cr0 + rs0; m0 = mn0;
        l1 = l1 * cr1 + rs1; m1 = mn1;
        #pragma unroll
        for (int nf = 0; nf < 12; nf++) {
            oa[nf][0] *= cr0; oa[nf][1] *= cr0;
            oa[nf][2] *= cr1; oa[nf][3] *= cr1;
        }
        __syncwarp();

        #pragma unroll
        for (int ks = 0; ks < 4; ks++) {
            uint32_t af[4];
            ldmx4(af, sP_u + (aRow * PSTR_H + ks * 16 + aK) * 2);
            #pragma unroll
            for (int nj = 0; nj < 6; nj++) {
                uint32_t bb[4];
                ldmx4(bb, fV_u + ((bRow + nj * 16) * VSTR_H + ks * 16 + bK) * 2);
                mma_f16(oa[nj * 2 + 0], af, &bb[0]);
                mma_f16(oa[nj * 2 + 1], af, &bb[2]);
            }
        }
        __syncwarp();
    }

    const float s0 = 1.0f / (l0 * 27.712812921102035f);
    const float s1 = 1.0f / (l1 * 27.712812921102035f);
    #pragma unroll
    for (int nf = 0; nf < 12; nf++) {
        const int col = nf * 8 + (lane & 3) * 2;
        *(__half2*)(O + baseQ + (long)rA * EMBD + col) =
            __floats2half2_rn(oa[nf][0] * s0, oa[nf][1] * s0);
        *(__half2*)(O + baseQ + (long)(rA + 8) * EMBD + col) =
            __floats2half2_rn(oa[nf][2] * s1, oa[nf][3] * s1);
    }
}

// ---------------- launch ----------------------------------------------------
extern "C" void kernel_launch(void* const* d_in, const int* in_sizes, int n_in,
                              void* d_out, int out_size) {
    const float* x     = (const float*)d_in[0];
    const float* ln1_g = (const float*)d_in[1];
    const float* ln1_b = (const float*)d_in[2];
    const float* wq    = (const float*)d_in[3];
    const float* bq    = (const float*)d_in[4];
    const float* wk    = (const float*)d_in[5];
    const float* bk    = (const float*)d_in[6];
    const float* wv    = (const float*)d_in[7];
    const float* bv    = (const float*)d_in[8];
    const float* wo    = (const float*)d_in[9];
    const float* bo    = (const float*)d_in[10];
    const float* ln2_g = (const float*)d_in[11];
    const float* ln2_b = (const float*)d_in[12];
    const float* w1    = (const float*)d_in[13];
    const float* b1    = (const float*)d_in[14];
    const float* w2    = (const float*)d_in[15];
    const float* b2    = (const float*)d_in[16];

    __half *yh, *qh, *kh, *vT, *oh, *zh, *hh, *wqkvT, *woT, *w1T, *w2T;
    float *x1, *bqkv;
    cudaGetSymbolAddress((void**)&yh,    g_yh);
    cudaGetSymbolAddress((void**)&qh,    g_qh);
    cudaGetSymbolAddress((void**)&kh,    g_kh);
    cudaGetSymbolAddress((void**)&vT,    g_vT);
    cudaGetSymbolAddress((void**)&oh,    g_oh);
    cudaGetSymbolAddress((void**)&zh,    g_zh);
    cudaGetSymbolAddress((void**)&hh,    g_hh);
    cudaGetSymbolAddress((void**)&x1,    g_x1);
    cudaGetSymbolAddress((void**)&wqkvT, g_wqkvT);
    cudaGetSymbolAddress((void**)&bqkv,  g_bqkv);
    cudaGetSymbolAddress((void**)&woT,   g_woT);
    cudaGetSymbolAddress((void**)&w1T,   g_w1T);
    cudaGetSymbolAddress((void**)&w2T,   g_w2T);

    cudaFuncSetAttribute(attn_h,
                         cudaFuncAttributeMaxDynamicSharedMemorySize, ATT_SMEM);
    cudaFuncSetAttribute(gemm_h<1>,
                         cudaFuncAttributeMaxDynamicSharedMemorySize, GMH_SMEM);
    cudaFuncSetAttribute(gemm_h<2>,
                         cudaFuncAttributeMaxDynamicSharedMemorySize, GMH_SMEM);
    cudaFuncSetAttribute(gemm_h<3>,
                         cudaFuncAttributeMaxDynamicSharedMemorySize, GMH_SMEM);

    convT_all<<<6912, dim3(32, 8)>>>(wq, wk, wv, wo, w1, w2);
    bias_cat_kernel<<<3, 256>>>(bq, bk, bv, bqkv);

    // LN1
    ln_kernel<<<TOK, 256>>>(x, ln1_g, ln1_b, yh);
    // fused QKV projection (EPI=3 writes g_qh/g_kh/g_vT directly)
    gemm_h<3><<<dim3(NQKV / 128, TOK / 128), 256, GMH_SMEM>>>(yh, wqkvT, bqkv, nullptr, nullptr, TOK, NQKV, EMBD);
    // attention
    attn_h<<<dim3(SEQ / FBM, NHEAD, NBATCH), 256, ATT_SMEM>>>(qh, kh, vT, oh);
    // output projection + residual (fp32 out)
    gemm_h<1><<<dim3(EMBD / 128, TOK / 128), 256, GMH_SMEM>>>(oh, woT, bo, x, x1, TOK, EMBD, EMBD);
    // LN2
    ln_kernel<<<TOK, 256>>>(x1, ln2_g, ln2_b, zh);
    // FFN
    gemm_h<2><<<dim3(DFF2 / 128, TOK / 128), 256, GMH_SMEM>>>(zh, w1T, b1, nullptr, hh, TOK, DFF2, EMBD);
    gemm_h<1><<<dim3(EMBD / 128, TOK / 128), 256, GMH_SMEM>>>(hh, w2T, b2, x1, d_out, TOK, EMBD, DFF2);
}